// round 12
// baseline (speedup 1.0000x reference)
#include <cuda_runtime.h>
#include <cuda_bf16.h>
#include <math.h>
#include <stdint.h>

#define BATCH 128
#define SEQ 176
#define DIN 20
#define DMODEL 256
#define DINNER 256
#define DX2 512
#define MROWS (BATCH*SEQ)   /* 22528 */
#define DSTATE 4
#define DTRANK 16
#define EPSF 1e-5f
#define NCOMB 264
#define KHEAD (SEQ*DMODEL)  /* 45056 */
#define CHUNK 352

// GEMM smem geometry (bf16 elements)
#define GSA 40              /* A row stride: 32 k + 8 pad */
#define GSBK 40             /* B row stride (k-contig) */
#define OFF_AL 10240
#define OFF_BH 20480
#define OFF_BL 25600
#define BUFSZ  30720
#define SMEM_GEMM (2*BUFSZ) /* 61440 */

// ---------------- scratch ----------------
__device__ __align__(16) float g_xln [MROWS*DMODEL];
__device__ __align__(16) float g_xz  [MROWS*DX2];
__device__ __align__(16) float g_dbl2[MROWS*NCOMB];
__device__ __align__(16) float g_y   [MROWS*DINNER];
__device__ __align__(16) float g_Wcomb[NCOMB*DMODEL];
__device__ __align__(16) float g_T1  [64*256];
__device__ __align__(16) float g_Wc  [16*256];
__device__ __align__(16) float g_Wc2 [16*256];
__device__ float g_bc1[64];
__device__ float g_bc2[16];
__device__ float g_Sc [16];
__device__ __align__(16) float g_Whead2[15*KHEAD];
__device__ float g_bhead[15];
__device__ float g_acc[15*128];

// ================= mma.sync helpers =================
__device__ __forceinline__ uint32_t smem_u32(const void* p) {
    uint32_t a;
    asm("{ .reg .u64 t; cvta.to.shared.u64 t, %1; cvt.u32.u64 %0, t; }" : "=r"(a) : "l"(p));
    return a;
}
__device__ __forceinline__ void ldsm_x4(uint32_t addr, uint32_t* r) {
    asm volatile("ldmatrix.sync.aligned.m8n8.x4.shared.b16 {%0,%1,%2,%3}, [%4];"
        : "=r"(r[0]),"=r"(r[1]),"=r"(r[2]),"=r"(r[3]) : "r"(addr));
}
__device__ __forceinline__ void mma_bf16(float* c, const uint32_t* a, const uint32_t* b) {
    asm volatile("mma.sync.aligned.m16n8k16.row.col.f32.bf16.bf16.f32 "
        "{%0,%1,%2,%3}, {%4,%5,%6,%7}, {%8,%9}, {%0,%1,%2,%3};"
        : "+f"(c[0]),"+f"(c[1]),"+f"(c[2]),"+f"(c[3])
        : "r"(a[0]),"r"(a[1]),"r"(a[2]),"r"(a[3]), "r"(b[0]),"r"(b[1]));
}
__device__ __forceinline__ float silu_f(float v) {
    return v / (1.f + __expf(-v));
}
__device__ __forceinline__ void split4(float4 v, uint2& hp, uint2& lp) {
    __nv_bfloat162 h01 = __floats2bfloat162_rn(v.x, v.y);
    __nv_bfloat162 h23 = __floats2bfloat162_rn(v.z, v.w);
    __nv_bfloat162 l01 = __floats2bfloat162_rn(v.x - __low2float(h01), v.y - __high2float(h01));
    __nv_bfloat162 l23 = __floats2bfloat162_rn(v.z - __low2float(h23), v.w - __high2float(h23));
    hp.x = *(uint32_t*)&h01; hp.y = *(uint32_t*)&h23;
    lp.x = *(uint32_t*)&l01; lp.y = *(uint32_t*)&l23;
}

// ---------------- GEMM core: 128 threads, warp tile 32m x 64n, double-buffered ----------------
#define GEMM_BODY(LD_A_EXPR)                                                         \
    extern __shared__ char sm_[];                                                    \
    const int tid  = threadIdx.x;                                                    \
    const int lane = tid & 31;                                                       \
    const int wm   = tid >> 5;          /* 0..3 */                                   \
    const int row0 = blockIdx.y * 128;                                               \
    const int col0 = blockIdx.x * 64;                                                \
    float acc[2][8][4];                                                              \
    _Pragma("unroll") for (int a_ = 0; a_ < 2; a_++)                                 \
        _Pragma("unroll") for (int b_ = 0; b_ < 8; b_++)                             \
            _Pragma("unroll") for (int c_ = 0; c_ < 4; c_++) acc[a_][b_][c_] = 0.f;  \
    float4 va[8], vb[4];                                                             \
    auto ld = [&](int k0c) {                                                         \
        _Pragma("unroll") for (int u = 0; u < 8; u++) {                              \
            int i = tid + u*128;                                                     \
            int r = i >> 3, c4 = (i & 7) << 2;                                       \
            va[u] = (LD_A_EXPR);                                                     \
        }                                                                            \
        _Pragma("unroll") for (int u = 0; u < 4; u++) {                              \
            int i = tid + u*128;                                                     \
            int r = i >> 3, c4 = (i & 7) << 2;                                       \
            vb[u] = (col0 + r < N)                                                   \
                  ? *(const float4*)(W + (size_t)(col0 + r) * K + k0c + c4)          \
                  : make_float4(0.f, 0.f, 0.f, 0.f);                                 \
        }                                                                            \
    };                                                                               \
    auto st = [&](int buf) {                                                         \
        char* base = sm_ + buf * BUFSZ;                                              \
        __nv_bfloat16* Ah = (__nv_bfloat16*)(base);                                  \
        __nv_bfloat16* Al = (__nv_bfloat16*)(base + OFF_AL);                         \
        __nv_bfloat16* Bh = (__nv_bfloat16*)(base + OFF_BH);                         \
        __nv_bfloat16* Bl = (__nv_bfloat16*)(base + OFF_BL);                         \
        _Pragma("unroll") for (int u = 0; u < 8; u++) {                              \
            int i = tid + u*128;                                                     \
            int r = i >> 3, c4 = (i & 7) << 2;                                       \
            uint2 hp, lp; split4(va[u], hp, lp);                                     \
            *(uint2*)(Ah + r*GSA + c4) = hp;                                         \
            *(uint2*)(Al + r*GSA + c4) = lp;                                         \
        }                                                                            \
        _Pragma("unroll") for (int u = 0; u < 4; u++) {                              \
            int i = tid + u*128;                                                     \
            int r = i >> 3, c4 = (i & 7) << 2;                                       \
            uint2 hp, lp; split4(vb[u], hp, lp);                                     \
            *(uint2*)(Bh + r*GSBK + c4) = hp;                                        \
            *(uint2*)(Bl + r*GSBK + c4) = lp;                                        \
        }                                                                            \
    };                                                                               \
    auto domma = [&](int buf) {                                                      \
        char* base = sm_ + buf * BUFSZ;                                              \
        const __nv_bfloat16* Ah = (const __nv_bfloat16*)(base);                      \
        const __nv_bfloat16* Al = (const __nv_bfloat16*)(base + OFF_AL);             \
        const __nv_bfloat16* Bh = (const __nv_bfloat16*)(base + OFF_BH);             \
        const __nv_bfloat16* Bl = (const __nv_bfloat16*)(base + OFF_BL);             \
        _Pragma("unroll") for (int ks = 0; ks < 2; ks++) {                           \
            const int kb = ks * 16;                                                  \
            uint32_t ah[2][4], al[2][4];                                             \
            _Pragma("unroll") for (int mi = 0; mi < 2; mi++) {                       \
                int r  = wm*32 + mi*16 + (lane & 15);                                \
                int kk = kb + ((lane & 16) ? 8 : 0);                                 \
                ldsm_x4(smem_u32(Ah + r*GSA + kk), ah[mi]);                          \
                ldsm_x4(smem_u32(Al + r*GSA + kk), al[mi]);                          \
            }                                                                        \
            uint32_t bh[8][2], bl[8][2];                                             \
            _Pragma("unroll") for (int np = 0; np < 4; np++) {                       \
                int nb = np*16;                                                      \
                int tile = lane >> 3, rowj = lane & 7;                               \
                int k_off = kb + (tile & 1) * 8;                                     \
                int n_off = nb + ((tile >> 1) & 1) * 8;                              \
                uint32_t r4[4];                                                      \
                ldsm_x4(smem_u32(Bh + (n_off + rowj)*GSBK + k_off), r4);             \
                bh[np*2][0]=r4[0]; bh[np*2][1]=r4[1];                                \
                bh[np*2+1][0]=r4[2]; bh[np*2+1][1]=r4[3];                            \
                ldsm_x4(smem_u32(Bl + (n_off + rowj)*GSBK + k_off), r4);             \
                bl[np*2][0]=r4[0]; bl[np*2][1]=r4[1];                                \
                bl[np*2+1][0]=r4[2]; bl[np*2+1][1]=r4[3];                            \
            }                                                                        \
            _Pragma("unroll") for (int mi = 0; mi < 2; mi++)                         \
                _Pragma("unroll") for (int ni = 0; ni < 8; ni++) {                   \
                    mma_bf16(acc[mi][ni], ah[mi], bh[ni]);                           \
                    mma_bf16(acc[mi][ni], ah[mi], bl[ni]);                           \
                    mma_bf16(acc[mi][ni], al[mi], bh[ni]);                           \
                }                                                                    \
        }                                                                            \
    };                                                                               \
    const int nch = K >> 5;                                                          \
    ld(0);                                                                           \
    st(0);                                                                           \
    __syncthreads();                                                                 \
    for (int ci = 0; ci < nch; ci++) {                                               \
        int cur = ci & 1;                                                            \
        if (ci + 1 < nch) ld((ci + 1) << 5);                                         \
        domma(cur);                                                                  \
        if (ci + 1 < nch) st(cur ^ 1);                                               \
        __syncthreads();                                                             \
    }                                                                                \
    _Pragma("unroll") for (int mi = 0; mi < 2; mi++) {                               \
        _Pragma("unroll") for (int ni = 0; ni < 8; ni++) {                           \
            int r = row0 + wm*32 + mi*16 + (lane >> 2);                              \
            int c = col0 + ni*8 + (lane & 3) * 2;                                    \
            _Pragma("unroll") for (int half = 0; half < 2; half++) {                 \
                int rr = r + half * 8;                                               \
                float v0 = acc[mi][ni][half*2 + 0];                                  \
                float v1 = acc[mi][ni][half*2 + 1];                                  \
                float* crow = C + (size_t)rr * N;                                    \
                if (c + 1 < N)      *(float2*)(crow + c) = make_float2(v0, v1);      \
                else if (c < N)     crow[c] = v0;                                    \
            }                                                                        \
        }                                                                            \
    }

__global__ __launch_bounds__(128)
void k_mma(const float* __restrict__ A, int lda,
           const float* __restrict__ W,
           float* __restrict__ C, int N, int K) {
    GEMM_BODY(*(const float4*)(A + (size_t)(row0 + r) * lda + k0c + c4))
}

__global__ __launch_bounds__(128)
void k_mma_conv(const float* __restrict__ convw, const float* __restrict__ convb,
                const float* __restrict__ W,
                float* __restrict__ C, int N, int K) {
    auto lda_conv = [&](int row0_, int r, int k0c, int c4) -> float4 {
        int row = row0_ + r;
        int k   = k0c + c4;
        const float* b1 = g_xz + (size_t)row * DX2 + k;
        float4 u1 = *(const float4*)b1;
        float4 u0 = ((row % SEQ) == 0) ? make_float4(0.f,0.f,0.f,0.f)
                                       : *(const float4*)(b1 - DX2);
        float4 cw0 = *(const float4*)(convw + 2*k);
        float4 cw1 = *(const float4*)(convw + 2*k + 4);
        float4 cb4 = *(const float4*)(convb + k);
        float v0 = fmaf(u0.x, cw0.x, fmaf(u1.x, cw0.y, cb4.x));
        float v1 = fmaf(u0.y, cw0.z, fmaf(u1.y, cw0.w, cb4.y));
        float v2 = fmaf(u0.z, cw1.x, fmaf(u1.z, cw1.y, cb4.z));
        float v3 = fmaf(u0.w, cw1.z, fmaf(u1.w, cw1.w, cb4.w));
        return make_float4(silu_f(v0), silu_f(v1), silu_f(v2), silu_f(v3));
    };
    GEMM_BODY(lda_conv(row0, r, k0c, c4))
}

// ---------------- precompute kernels ----------------
__global__ __launch_bounds__(256)
void k_wcomb(const float* __restrict__ dtw, const float* __restrict__ xpw) {
    int r = blockIdx.x, c = threadIdx.x;
    float v;
    if (r < 256) {
        v = 0.f;
        #pragma unroll
        for (int j = 0; j < 16; j++) v = fmaf(dtw[r*16 + j], xpw[j*256 + c], v);
    } else {
        v = xpw[(r - 256 + 16)*256 + c];
    }
    g_Wcomb[r*256 + c] = v;
}

__global__ __launch_bounds__(256)
void k_t1(const float* __restrict__ l5aw, const float* __restrict__ l5ab,
          const float* __restrict__ l5bw, const float* __restrict__ l5bb) {
    int r = blockIdx.x, c = threadIdx.x;
    __shared__ float wr[128];
    if (c < 128) wr[c] = l5bw[r*128 + c];
    __syncthreads();
    float v = 0.f;
    for (int j = 0; j < 128; j++) v = fmaf(wr[j], l5aw[j*256 + c], v);
    g_T1[r*256 + c] = v;
    if (c == 0) {
        float b = l5bb[r];
        for (int j = 0; j < 128; j++) b = fmaf(wr[j], l5ab[j], b);
        g_bc1[r] = b;
    }
}

__global__ __launch_bounds__(256)
void k_t2(const float* __restrict__ l5cw, const float* __restrict__ l5cb) {
    int r = blockIdx.x, c = threadIdx.x;
    __shared__ float wr[64];
    __shared__ float red[8];
    if (c < 64) wr[c] = l5cw[r*64 + c];
    __syncthreads();
    float v = 0.f;
    for (int j = 0; j < 64; j++) v = fmaf(wr[j], g_T1[j*256 + c], v);
    g_Wc[r*256 + c] = v;
    float s = v;
    #pragma unroll
    for (int o = 16; o > 0; o >>= 1) s += __shfl_xor_sync(0xffffffffu, s, o);
    if ((c & 31) == 0) red[c >> 5] = s;
    __syncthreads();
    if (c == 0) {
        float t = 0.f;
        for (int j = 0; j < 8; j++) t += red[j];
        g_Sc[r] = t;
        float b = l5cb[r];
        for (int j = 0; j < 64; j++) b = fmaf(wr[j], g_bc1[j], b);
        g_bc2[r] = b;
    }
}

// Wc2[o,j] = sum_c Wc[o,c] * Wout[c,j]
__global__ __launch_bounds__(256)
void k_wc2(const float* __restrict__ outw) {
    int o = blockIdx.x, j = threadIdx.x;
    __shared__ float wcs[256];
    wcs[j] = g_Wc[o*256 + j];
    __syncthreads();
    float v = 0.f;
    for (int c = 0; c < 256; c++) v = fmaf(wcs[c], outw[c*256 + j], v);
    g_Wc2[o*256 + j] = v;
}

// Whead2[i,l,c] = s_l * sum_o fc3_w[i,l*16+o] * Wc2[o,c]
__global__ __launch_bounds__(256)
void k_t3(const float* __restrict__ fc3w, const float* __restrict__ bn5g) {
    int l = blockIdx.x, i = blockIdx.y, c = threadIdx.x;
    __shared__ float f[16];
    if (c < 16) f[c] = fc3w[i*2816 + l*16 + c];
    __syncthreads();
    float v = 0.f;
    #pragma unroll
    for (int o = 0; o < 16; o++) v = fmaf(f[o], g_Wc2[o*256 + c], v);
    float sl = bn5g[l] * rsqrtf(1.0f + EPSF);
    g_Whead2[((size_t)i*SEQ + l)*256 + c] = v * sl;
}

__global__ __launch_bounds__(512)
void k_bias(const float* __restrict__ fc3w, const float* __restrict__ fc3b,
            const float* __restrict__ bn5b) {
    int w = threadIdx.x >> 5, lane = threadIdx.x & 31;
    for (int p = threadIdx.x; p < 15*128; p += 512) g_acc[p] = 0.f;
    if (w >= 15) return;
    float s = 0.f;
    for (int idx = lane; idx < 2816; idx += 32) {
        int l = idx >> 4, o = idx & 15;
        s = fmaf(fc3w[w*2816 + idx], g_bc2[o] + bn5b[l]*g_Sc[o], s);
    }
    #pragma unroll
    for (int o = 16; o > 0; o >>= 1) s += __shfl_xor_sync(0xffffffffu, s, o);
    if (lane == 0) g_bhead[w] = fc3b[w] + s;
}

// ---------------- front: warp-per-row ----------------
__global__ __launch_bounds__(256)
void k_front(const float* __restrict__ x,
             const float* __restrict__ w, const float* __restrict__ b,
             const float* __restrict__ bn_g, const float* __restrict__ bn_b,
             const float* __restrict__ ln_g, const float* __restrict__ ln_b) {
    const int warp = threadIdx.x >> 5, lane = threadIdx.x & 31;
    const int row  = blockIdx.x * 8 + warp;
    const int l    = row % SEQ;
    float xv[DIN];
    #pragma unroll
    for (int k = 0; k < DIN; k++) xv[k] = __ldg(x + row*DIN + k);
    const float scale = __ldg(bn_g + l) * rsqrtf(1.0f + EPSF);
    const float shift = __ldg(bn_b + l);
    float v[8];
    float s = 0.f;
    #pragma unroll
    for (int j = 0; j < 8; j++) {
        int c = lane + 32*j;
        float acc = __ldg(b + c);
        const float* wc = w + c*DIN;
        #pragma unroll
        for (int k = 0; k < DIN; k++) acc = fmaf(xv[k], __ldg(wc + k), acc);
        acc = acc * scale + shift;
        acc = acc >= 0.f ? acc : 0.01f * acc;
        v[j] = acc;
        s += acc;
    }
    #pragma unroll
    for (int o = 16; o > 0; o >>= 1) s += __shfl_xor_sync(0xffffffffu, s, o);
    const float mu = s * (1.0f/256.0f);
    float q = 0.f;
    #pragma unroll
    for (int j = 0; j < 8; j++) { float d = v[j] - mu; q += d*d; }
    #pragma unroll
    for (int o = 16; o > 0; o >>= 1) q += __shfl_xor_sync(0xffffffffu, q, o);
    const float rstd = rsqrtf(q * (1.0f/256.0f) + EPSF);
    #pragma unroll
    for (int j = 0; j < 8; j++) {
        int c = lane + 32*j;
        g_xln[row*DMODEL + c] = (v[j] - mu) * rstd * __ldg(ln_g + c) + __ldg(ln_b + c);
    }
}

// ---------------- selective scan ----------------
__global__ __launch_bounds__(128)
void k_scan(const float* __restrict__ A_log, const float* __restrict__ Dp,
            const float* __restrict__ dtb,
            const float* __restrict__ convw, const float* __restrict__ convb) {
    int b = blockIdx.x;
    int d = blockIdx.y * 128 + threadIdx.x;
    float A0 = -expf(A_log[d*4+0]);
    float A1 = -expf(A_log[d*4+1]);
    float A2 = -expf(A_log[d*4+2]);
    float A3 = -expf(A_log[d*4+3]);
    float Dd = Dp[d];
    float bdt = dtb[d];
    float w0 = convw[2*d], w1 = convw[2*d+1], cb = convb[d];
    float h0 = 0.f, h1 = 0.f, h2 = 0.f, h3 = 0.f;
    float up = 0.f;
    const size_t base_row = (size_t)b * SEQ;
    float u_n   = g_xz[(base_row)*DX2 + d];
    float z_n   = g_xz[(base_row)*DX2 + DINNER + d];
    float dtp_n = g_dbl2[(base_row)*NCOMB + d];
    float4 bc0_n = *(const float4*)(g_dbl2 + (base_row)*NCOMB + 256);
    float4 bc1_n = *(const float4*)(g_dbl2 + (base_row)*NCOMB + 260);
    for (int t = 0; t < SEQ; t++) {
        float u = u_n, z = z_n, dtp0 = dtp_n;
        float4 bc0 = bc0_n, bc1 = bc1_n;
        if (t + 1 < SEQ) {
            size_t row1 = base_row + t + 1;
            u_n   = g_xz[row1*DX2 + d];
            z_n   = g_xz[row1*DX2 + DINNER + d];
            dtp_n = g_dbl2[row1*NCOMB + d];
            bc0_n = *(const float4*)(g_dbl2 + row1*NCOMB + 256);
            bc1_n = *(const float4*)(g_dbl2 + row1*NCOMB + 260);
        }
        float cv  = fmaf(up, w0, fmaf(u, w1, cb));
        float xc  = cv / (1.f + __expf(-cv));
        up = u;
        float dtp = dtp0 + bdt;
        float dt  = fmaxf(dtp, 0.f) + log1pf(__expf(-fabsf(dtp)));
        float dtxc = dt * xc;
        h0 = fmaf(h0, __expf(dt * A0), dtxc * bc0.x);
        h1 = fmaf(h1, __expf(dt * A1), dtxc * bc0.y);
        h2 = fmaf(h2, __expf(dt * A2), dtxc * bc0.z);
        h3 = fmaf(h3, __expf(dt * A3), dtxc * bc0.w);
        float y = h0*bc1.x + h1*bc1.y + h2*bc1.z + h3*bc1.w;
        y = fmaf(Dd, xc, y);
        float sz = z / (1.f + __expf(-z));
        g_y[(base_row + t) * DINNER + d] = y * sz;
    }
}

// ---------------- final ----------------
__global__ __launch_bounds__(256)
void k_final() {
    __shared__ float sW[15][CHUNK];
    const int cx = blockIdx.x;
    const int bg = blockIdx.y;
    const int k0 = cx * CHUNK;
    const int tid = threadIdx.x;
    for (int idx = tid; idx < 15*CHUNK; idx += 256) {
        int i = idx / CHUNK, k = idx - i*CHUNK;
        sW[i][k] = g_Whead2[(size_t)i*KHEAD + k0 + k];
    }
    __syncthreads();
    const int w = tid >> 5, lane = tid & 31;
    #pragma unroll
    for (int bi = 0; bi < 2; bi++) {
        int b = bg * 16 + w * 2 + bi;
        const float* yrow = g_y + (size_t)b * KHEAD + k0;
        #pragma unroll 1
        for (int i = 0; i < 15; i++) {
            float s = 0.f;
            #pragma unroll
            for (int k = lane; k < CHUNK; k += 32) s = fmaf(yrow[k], sW[i][k], s);
            #pragma unroll
            for (int o = 16; o > 0; o >>= 1) s += __shfl_xor_sync(0xffffffffu, s, o);
            if (lane == 0) atomicAdd(&g_acc[i*128 + b], s);
        }
    }
}

__global__ __launch_bounds__(256)
void k_sig(float* __restrict__ out) {
    int p = blockIdx.x * 256 + threadIdx.x;
    if (p >= 15*128) return;
    int b = p / 15, i = p - b*15;
    out[p] = 1.f / (1.f + expf(-(g_acc[i*128 + b] + g_bhead[i])));
}

// ---------------- launch ----------------
extern "C" void kernel_launch(void* const* d_in, const int* in_sizes, int n_in,
                              void* d_out, int out_size) {
    const float* x         = (const float*)d_in[0];
    const float* lin1_w    = (const float*)d_in[1];
    const float* lin1_b    = (const float*)d_in[2];
    const float* bn1_g     = (const float*)d_in[3];
    const float* bn1_b     = (const float*)d_in[4];
    const float* ln_g      = (const float*)d_in[5];
    const float* ln_b      = (const float*)d_in[6];
    const float* in_proj_w = (const float*)d_in[7];
    const float* conv_w    = (const float*)d_in[8];
    const float* conv_b    = (const float*)d_in[9];
    const float* x_proj_w  = (const float*)d_in[10];
    const float* dt_proj_w = (const float*)d_in[11];
    const float* dt_proj_b = (const float*)d_in[12];
    const float* A_log     = (const float*)d_in[13];
    const float* Dp        = (const float*)d_in[14];
    const float* out_proj_w= (const float*)d_in[15];
    const float* bn5_g     = (const float*)d_in[16];
    const float* bn5_b     = (const float*)d_in[17];
    const float* l5a_w     = (const float*)d_in[18];
    const float* l5a_b     = (const float*)d_in[19];
    const float* l5b_w     = (const float*)d_in[20];
    const float* l5b_b     = (const float*)d_in[21];
    const float* l5c_w     = (const float*)d_in[22];
    const float* l5c_b     = (const float*)d_in[23];
    const float* fc3_w     = (const float*)d_in[24];
    const float* fc3_b     = (const float*)d_in[25];

    float *p_xln, *p_xz, *p_dbl2, *p_Wcomb;
    cudaGetSymbolAddress((void**)&p_xln,   g_xln);
    cudaGetSymbolAddress((void**)&p_xz,    g_xz);
    cudaGetSymbolAddress((void**)&p_dbl2,  g_dbl2);
    cudaGetSymbolAddress((void**)&p_Wcomb, g_Wcomb);

    cudaFuncSetAttribute(k_mma,      cudaFuncAttributeMaxDynamicSharedMemorySize, SMEM_GEMM);
    cudaFuncSetAttribute(k_mma_conv, cudaFuncAttributeMaxDynamicSharedMemorySize, SMEM_GEMM);

    const int GY = MROWS / 128;   // 176

    // 0: front
    k_front<<<MROWS/8, 256>>>(x, lin1_w, lin1_b, bn1_g, bn1_b, ln_g, ln_b);
    // 1: wcomb
    k_wcomb<<<NCOMB, 256>>>(dt_proj_w, x_proj_w);
    // 2: t1
    k_t1<<<64, 256>>>(l5a_w, l5a_b, l5b_w, l5b_b);
    // 3: in_proj  [M,256]@[512,256]^T   <-- profiled slot
    k_mma<<<dim3(8, GY), 128, SMEM_GEMM>>>(p_xln, DMODEL, in_proj_w, p_xz, DX2, DMODEL);
    // 4: t2
    k_t2<<<16, 256>>>(l5c_w, l5c_b);
    // 5: Wc2 = Wc @ Wout
    k_wc2<<<16, 256>>>(out_proj_w);
    // 6: t3 -> Whead2 directly
    k_t3<<<dim3(SEQ, 15), 256>>>(fc3_w, bn5_g);
    // 7: bias (+ zero acc)
    k_bias<<<1, 512>>>(fc3_w, fc3_b, bn5_b);
    // 8: fused conv+silu + (dt_pre|B|C) GEMM
    k_mma_conv<<<dim3(5, GY), 128, SMEM_GEMM>>>(conv_w, conv_b, p_Wcomb, p_dbl2, NCOMB, DINNER);
    // 9: scan
    k_scan<<<dim3(BATCH, 2), 128>>>(A_log, Dp, dt_proj_b, conv_w, conv_b);
    // 10: folded head
    k_final<<<dim3(KHEAD/CHUNK, 8), 256>>>();
    // 11: sigmoid
    k_sig<<<(15*128 + 255)/256, 256>>>((float*)d_out);
}

// round 13
// speedup vs baseline: 1.0829x; 1.0829x over previous
#include <cuda_runtime.h>
#include <cuda_bf16.h>
#include <math.h>
#include <stdint.h>

#define BATCH 128
#define SEQ 176
#define DIN 20
#define DMODEL 256
#define DINNER 256
#define DX2 512
#define MROWS (BATCH*SEQ)   /* 22528 */
#define DSTATE 4
#define DTRANK 16
#define EPSF 1e-5f
#define NCOMB 264
#define KHEAD (SEQ*DMODEL)  /* 45056 */
#define CHUNK 352

// GEMM smem geometry (bf16 elements)
#define GSA 40              /* A row stride: 32 k + 8 pad */
#define GSBK 40             /* B row stride (k-contig) */
#define OFF_AL 10240
#define OFF_BH 20480
#define OFF_BL 25600
#define BUFSZ  30720
#define SMEM_GEMM (2*BUFSZ) /* 61440 */

// ---------------- scratch ----------------
__device__ __align__(16) float g_xln [MROWS*DMODEL];
__device__ __align__(16) float g_xz  [MROWS*DX2];
__device__ __align__(16) float g_dbl2[MROWS*NCOMB];
__device__ __align__(16) float g_y   [MROWS*DINNER];
__device__ __align__(16) float g_Wcomb[NCOMB*DMODEL];
__device__ __align__(16) float g_T1  [64*256];
__device__ __align__(16) float g_Wc  [16*256];
__device__ __align__(16) float g_Wc2 [16*256];
__device__ float g_bc1[64];
__device__ float g_bc2[16];
__device__ float g_Sc [16];
__device__ __align__(16) float g_Whead2[15*KHEAD];
__device__ float g_bhead[15];
__device__ float g_acc[15*128];

// ================= mma.sync helpers =================
__device__ __forceinline__ uint32_t smem_u32(const void* p) {
    uint32_t a;
    asm("{ .reg .u64 t; cvta.to.shared.u64 t, %1; cvt.u32.u64 %0, t; }" : "=r"(a) : "l"(p));
    return a;
}
__device__ __forceinline__ void ldsm_x4(uint32_t addr, uint32_t* r) {
    asm volatile("ldmatrix.sync.aligned.m8n8.x4.shared.b16 {%0,%1,%2,%3}, [%4];"
        : "=r"(r[0]),"=r"(r[1]),"=r"(r[2]),"=r"(r[3]) : "r"(addr));
}
__device__ __forceinline__ void mma_bf16(float* c, const uint32_t* a, const uint32_t* b) {
    asm volatile("mma.sync.aligned.m16n8k16.row.col.f32.bf16.bf16.f32 "
        "{%0,%1,%2,%3}, {%4,%5,%6,%7}, {%8,%9}, {%0,%1,%2,%3};"
        : "+f"(c[0]),"+f"(c[1]),"+f"(c[2]),"+f"(c[3])
        : "r"(a[0]),"r"(a[1]),"r"(a[2]),"r"(a[3]), "r"(b[0]),"r"(b[1]));
}
__device__ __forceinline__ float silu_f(float v) {
    return v / (1.f + __expf(-v));
}
__device__ __forceinline__ void split4(float4 v, uint2& hp, uint2& lp) {
    __nv_bfloat162 h01 = __floats2bfloat162_rn(v.x, v.y);
    __nv_bfloat162 h23 = __floats2bfloat162_rn(v.z, v.w);
    __nv_bfloat162 l01 = __floats2bfloat162_rn(v.x - __low2float(h01), v.y - __high2float(h01));
    __nv_bfloat162 l23 = __floats2bfloat162_rn(v.z - __low2float(h23), v.w - __high2float(h23));
    hp.x = *(uint32_t*)&h01; hp.y = *(uint32_t*)&h23;
    lp.x = *(uint32_t*)&l01; lp.y = *(uint32_t*)&l23;
}

// ---------------- GEMM core: 256 threads, 8 warps (4 wm x 2 wn), double-buffered ----------------
#define GEMM_BODY(LD_A_EXPR)                                                         \
    extern __shared__ char sm_[];                                                    \
    const int tid  = threadIdx.x;                                                    \
    const int lane = tid & 31;                                                       \
    const int wid  = tid >> 5;                                                       \
    const int wm   = wid & 3;                                                        \
    const int wn   = wid >> 2;                                                       \
    const int row0 = blockIdx.y * 128;                                               \
    const int col0 = blockIdx.x * 64;                                                \
    float acc[2][4][4];                                                              \
    _Pragma("unroll") for (int a_ = 0; a_ < 2; a_++)                                 \
        _Pragma("unroll") for (int b_ = 0; b_ < 4; b_++)                             \
            _Pragma("unroll") for (int c_ = 0; c_ < 4; c_++) acc[a_][b_][c_] = 0.f;  \
    float4 va[4], vb[2];                                                             \
    auto ld = [&](int k0c) {                                                         \
        _Pragma("unroll") for (int u = 0; u < 4; u++) {                              \
            int i = tid + u*256;                                                     \
            int r = i >> 3, c4 = (i & 7) << 2;                                       \
            va[u] = (LD_A_EXPR);                                                     \
        }                                                                            \
        _Pragma("unroll") for (int u = 0; u < 2; u++) {                              \
            int i = tid + u*256;                                                     \
            int r = i >> 3, c4 = (i & 7) << 2;                                       \
            vb[u] = (col0 + r < N)                                                   \
                  ? *(const float4*)(W + (size_t)(col0 + r) * K + k0c + c4)          \
                  : make_float4(0.f, 0.f, 0.f, 0.f);                                 \
        }                                                                            \
    };                                                                               \
    auto st = [&](int buf) {                                                         \
        char* base = sm_ + buf * BUFSZ;                                              \
        __nv_bfloat16* Ah = (__nv_bfloat16*)(base);                                  \
        __nv_bfloat16* Al = (__nv_bfloat16*)(base + OFF_AL);                         \
        __nv_bfloat16* Bh = (__nv_bfloat16*)(base + OFF_BH);                         \
        __nv_bfloat16* Bl = (__nv_bfloat16*)(base + OFF_BL);                         \
        _Pragma("unroll") for (int u = 0; u < 4; u++) {                              \
            int i = tid + u*256;                                                     \
            int r = i >> 3, c4 = (i & 7) << 2;                                       \
            uint2 hp, lp; split4(va[u], hp, lp);                                     \
            *(uint2*)(Ah + r*GSA + c4) = hp;                                         \
            *(uint2*)(Al + r*GSA + c4) = lp;                                         \
        }                                                                            \
        _Pragma("unroll") for (int u = 0; u < 2; u++) {                              \
            int i = tid + u*256;                                                     \
            int r = i >> 3, c4 = (i & 7) << 2;                                       \
            uint2 hp, lp; split4(vb[u], hp, lp);                                     \
            *(uint2*)(Bh + r*GSBK + c4) = hp;                                        \
            *(uint2*)(Bl + r*GSBK + c4) = lp;                                        \
        }                                                                            \
    };                                                                               \
    auto domma = [&](int buf) {                                                      \
        char* base = sm_ + buf * BUFSZ;                                              \
        const __nv_bfloat16* Ah = (const __nv_bfloat16*)(base);                      \
        const __nv_bfloat16* Al = (const __nv_bfloat16*)(base + OFF_AL);             \
        const __nv_bfloat16* Bh = (const __nv_bfloat16*)(base + OFF_BH);             \
        const __nv_bfloat16* Bl = (const __nv_bfloat16*)(base + OFF_BL);             \
        _Pragma("unroll") for (int ks = 0; ks < 2; ks++) {                           \
            const int kb = ks * 16;                                                  \
            uint32_t ah[2][4], al[2][4];                                             \
            _Pragma("unroll") for (int mi = 0; mi < 2; mi++) {                       \
                int r  = wm*32 + mi*16 + (lane & 15);                                \
                int kk = kb + ((lane & 16) ? 8 : 0);                                 \
                ldsm_x4(smem_u32(Ah + r*GSA + kk), ah[mi]);                          \
                ldsm_x4(smem_u32(Al + r*GSA + kk), al[mi]);                          \
            }                                                                        \
            uint32_t bh[4][2], bl[4][2];                                             \
            _Pragma("unroll") for (int np = 0; np < 2; np++) {                       \
                int nb = wn*32 + np*16;                                              \
                int tile = lane >> 3, rowj = lane & 7;                               \
                int k_off = kb + (tile & 1) * 8;                                     \
                int n_off = nb + ((tile >> 1) & 1) * 8;                              \
                uint32_t r4[4];                                                      \
                ldsm_x4(smem_u32(Bh + (n_off + rowj)*GSBK + k_off), r4);             \
                bh[np*2][0]=r4[0]; bh[np*2][1]=r4[1];                                \
                bh[np*2+1][0]=r4[2]; bh[np*2+1][1]=r4[3];                            \
                ldsm_x4(smem_u32(Bl + (n_off + rowj)*GSBK + k_off), r4);             \
                bl[np*2][0]=r4[0]; bl[np*2][1]=r4[1];                                \
                bl[np*2+1][0]=r4[2]; bl[np*2+1][1]=r4[3];                            \
            }                                                                        \
            _Pragma("unroll") for (int mi = 0; mi < 2; mi++)                         \
                _Pragma("unroll") for (int ni = 0; ni < 4; ni++) {                   \
                    mma_bf16(acc[mi][ni], ah[mi], bh[ni]);                           \
                    mma_bf16(acc[mi][ni], ah[mi], bl[ni]);                           \
                    mma_bf16(acc[mi][ni], al[mi], bh[ni]);                           \
                }                                                                    \
        }                                                                            \
    };                                                                               \
    const int nch = K >> 5;                                                          \
    ld(0);                                                                           \
    st(0);                                                                           \
    __syncthreads();                                                                 \
    for (int ci = 0; ci < nch; ci++) {                                               \
        int cur = ci & 1;                                                            \
        if (ci + 1 < nch) ld((ci + 1) << 5);                                         \
        domma(cur);                                                                  \
        if (ci + 1 < nch) st(cur ^ 1);                                               \
        __syncthreads();                                                             \
    }                                                                                \
    _Pragma("unroll") for (int mi = 0; mi < 2; mi++) {                               \
        _Pragma("unroll") for (int ni = 0; ni < 4; ni++) {                           \
            int r = row0 + wm*32 + mi*16 + (lane >> 2);                              \
            int c = col0 + wn*32 + ni*8 + (lane & 3) * 2;                            \
            _Pragma("unroll") for (int half = 0; half < 2; half++) {                 \
                int rr = r + half * 8;                                               \
                float v0 = acc[mi][ni][half*2 + 0];                                  \
                float v1 = acc[mi][ni][half*2 + 1];                                  \
                float* crow = C + (size_t)rr * N;                                    \
                if (c + 1 < N)      *(float2*)(crow + c) = make_float2(v0, v1);      \
                else if (c < N)     crow[c] = v0;                                    \
            }                                                                        \
        }                                                                            \
    }

__global__ __launch_bounds__(256)
void k_mma(const float* __restrict__ A, int lda,
           const float* __restrict__ W,
           float* __restrict__ C, int N, int K) {
    GEMM_BODY(*(const float4*)(A + (size_t)(row0 + r) * lda + k0c + c4))
}

__global__ __launch_bounds__(256)
void k_mma_conv(const float* __restrict__ convw, const float* __restrict__ convb,
                const float* __restrict__ W,
                float* __restrict__ C, int N, int K) {
    auto lda_conv = [&](int row0_, int r, int k0c, int c4) -> float4 {
        int row = row0_ + r;
        int k   = k0c + c4;
        const float* b1 = g_xz + (size_t)row * DX2 + k;
        float4 u1 = *(const float4*)b1;
        float4 u0 = ((row % SEQ) == 0) ? make_float4(0.f,0.f,0.f,0.f)
                                       : *(const float4*)(b1 - DX2);
        float4 cw0 = *(const float4*)(convw + 2*k);
        float4 cw1 = *(const float4*)(convw + 2*k + 4);
        float4 cb4 = *(const float4*)(convb + k);
        float v0 = fmaf(u0.x, cw0.x, fmaf(u1.x, cw0.y, cb4.x));
        float v1 = fmaf(u0.y, cw0.z, fmaf(u1.y, cw0.w, cb4.y));
        float v2 = fmaf(u0.z, cw1.x, fmaf(u1.z, cw1.y, cb4.z));
        float v3 = fmaf(u0.w, cw1.z, fmaf(u1.w, cw1.w, cb4.w));
        return make_float4(silu_f(v0), silu_f(v1), silu_f(v2), silu_f(v3));
    };
    GEMM_BODY(lda_conv(row0, r, k0c, c4))
}

// ---------------- precompute kernels ----------------
__global__ __launch_bounds__(256)
void k_wcomb(const float* __restrict__ dtw, const float* __restrict__ xpw) {
    int r = blockIdx.x, c = threadIdx.x;
    float v;
    if (r < 256) {
        v = 0.f;
        #pragma unroll
        for (int j = 0; j < 16; j++) v = fmaf(dtw[r*16 + j], xpw[j*256 + c], v);
    } else {
        v = xpw[(r - 256 + 16)*256 + c];
    }
    g_Wcomb[r*256 + c] = v;
}

__global__ __launch_bounds__(256)
void k_t1(const float* __restrict__ l5aw, const float* __restrict__ l5ab,
          const float* __restrict__ l5bw, const float* __restrict__ l5bb) {
    int r = blockIdx.x, c = threadIdx.x;
    __shared__ float wr[128];
    if (c < 128) wr[c] = l5bw[r*128 + c];
    __syncthreads();
    float v = 0.f;
    for (int j = 0; j < 128; j++) v = fmaf(wr[j], l5aw[j*256 + c], v);
    g_T1[r*256 + c] = v;
    if (c == 0) {
        float b = l5bb[r];
        for (int j = 0; j < 128; j++) b = fmaf(wr[j], l5ab[j], b);
        g_bc1[r] = b;
    }
}

__global__ __launch_bounds__(256)
void k_t2(const float* __restrict__ l5cw, const float* __restrict__ l5cb) {
    int r = blockIdx.x, c = threadIdx.x;
    __shared__ float wr[64];
    __shared__ float red[8];
    if (c < 64) wr[c] = l5cw[r*64 + c];
    __syncthreads();
    float v = 0.f;
    for (int j = 0; j < 64; j++) v = fmaf(wr[j], g_T1[j*256 + c], v);
    g_Wc[r*256 + c] = v;
    float s = v;
    #pragma unroll
    for (int o = 16; o > 0; o >>= 1) s += __shfl_xor_sync(0xffffffffu, s, o);
    if ((c & 31) == 0) red[c >> 5] = s;
    __syncthreads();
    if (c == 0) {
        float t = 0.f;
        for (int j = 0; j < 8; j++) t += red[j];
        g_Sc[r] = t;
        float b = l5cb[r];
        for (int j = 0; j < 64; j++) b = fmaf(wr[j], g_bc1[j], b);
        g_bc2[r] = b;
    }
}

// Wc2[o,j] = sum_c Wc[o,c] * Wout[c,j]
__global__ __launch_bounds__(256)
void k_wc2(const float* __restrict__ outw) {
    int o = blockIdx.x, j = threadIdx.x;
    __shared__ float wcs[256];
    wcs[j] = g_Wc[o*256 + j];
    __syncthreads();
    float v = 0.f;
    for (int c = 0; c < 256; c++) v = fmaf(wcs[c], outw[c*256 + j], v);
    g_Wc2[o*256 + j] = v;
}

// Whead2[i,l,c] = s_l * sum_o fc3_w[i,l*16+o] * Wc2[o,c]
__global__ __launch_bounds__(256)
void k_t3(const float* __restrict__ fc3w, const float* __restrict__ bn5g) {
    int l = blockIdx.x, i = blockIdx.y, c = threadIdx.x;
    __shared__ float f[16];
    if (c < 16) f[c] = fc3w[i*2816 + l*16 + c];
    __syncthreads();
    float v = 0.f;
    #pragma unroll
    for (int o = 0; o < 16; o++) v = fmaf(f[o], g_Wc2[o*256 + c], v);
    float sl = bn5g[l] * rsqrtf(1.0f + EPSF);
    g_Whead2[((size_t)i*SEQ + l)*256 + c] = v * sl;
}

__global__ __launch_bounds__(512)
void k_bias(const float* __restrict__ fc3w, const float* __restrict__ fc3b,
            const float* __restrict__ bn5b) {
    int w = threadIdx.x >> 5, lane = threadIdx.x & 31;
    for (int p = threadIdx.x; p < 15*128; p += 512) g_acc[p] = 0.f;
    if (w >= 15) return;
    float s = 0.f;
    for (int idx = lane; idx < 2816; idx += 32) {
        int l = idx >> 4, o = idx & 15;
        s = fmaf(fc3w[w*2816 + idx], g_bc2[o] + bn5b[l]*g_Sc[o], s);
    }
    #pragma unroll
    for (int o = 16; o > 0; o >>= 1) s += __shfl_xor_sync(0xffffffffu, s, o);
    if (lane == 0) g_bhead[w] = fc3b[w] + s;
}

// ---------------- front: warp-per-row ----------------
__global__ __launch_bounds__(256)
void k_front(const float* __restrict__ x,
             const float* __restrict__ w, const float* __restrict__ b,
             const float* __restrict__ bn_g, const float* __restrict__ bn_b,
             const float* __restrict__ ln_g, const float* __restrict__ ln_b) {
    const int warp = threadIdx.x >> 5, lane = threadIdx.x & 31;
    const int row  = blockIdx.x * 8 + warp;
    const int l    = row % SEQ;
    float xv[DIN];
    #pragma unroll
    for (int k = 0; k < DIN; k++) xv[k] = __ldg(x + row*DIN + k);
    const float scale = __ldg(bn_g + l) * rsqrtf(1.0f + EPSF);
    const float shift = __ldg(bn_b + l);
    float v[8];
    float s = 0.f;
    #pragma unroll
    for (int j = 0; j < 8; j++) {
        int c = lane + 32*j;
        float acc = __ldg(b + c);
        const float* wc = w + c*DIN;
        #pragma unroll
        for (int k = 0; k < DIN; k++) acc = fmaf(xv[k], __ldg(wc + k), acc);
        acc = acc * scale + shift;
        acc = acc >= 0.f ? acc : 0.01f * acc;
        v[j] = acc;
        s += acc;
    }
    #pragma unroll
    for (int o = 16; o > 0; o >>= 1) s += __shfl_xor_sync(0xffffffffu, s, o);
    const float mu = s * (1.0f/256.0f);
    float q = 0.f;
    #pragma unroll
    for (int j = 0; j < 8; j++) { float d = v[j] - mu; q += d*d; }
    #pragma unroll
    for (int o = 16; o > 0; o >>= 1) q += __shfl_xor_sync(0xffffffffu, q, o);
    const float rstd = rsqrtf(q * (1.0f/256.0f) + EPSF);
    #pragma unroll
    for (int j = 0; j < 8; j++) {
        int c = lane + 32*j;
        g_xln[row*DMODEL + c] = (v[j] - mu) * rstd * __ldg(ln_g + c) + __ldg(ln_b + c);
    }
}

// ---------------- selective scan ----------------
__global__ __launch_bounds__(128)
void k_scan(const float* __restrict__ A_log, const float* __restrict__ Dp,
            const float* __restrict__ dtb,
            const float* __restrict__ convw, const float* __restrict__ convb) {
    int b = blockIdx.x;
    int d = blockIdx.y * 128 + threadIdx.x;
    float A0 = -expf(A_log[d*4+0]);
    float A1 = -expf(A_log[d*4+1]);
    float A2 = -expf(A_log[d*4+2]);
    float A3 = -expf(A_log[d*4+3]);
    float Dd = Dp[d];
    float bdt = dtb[d];
    float w0 = convw[2*d], w1 = convw[2*d+1], cb = convb[d];
    float h0 = 0.f, h1 = 0.f, h2 = 0.f, h3 = 0.f;
    float up = 0.f;
    const size_t base_row = (size_t)b * SEQ;
    float u_n   = g_xz[(base_row)*DX2 + d];
    float z_n   = g_xz[(base_row)*DX2 + DINNER + d];
    float dtp_n = g_dbl2[(base_row)*NCOMB + d];
    float4 bc0_n = *(const float4*)(g_dbl2 + (base_row)*NCOMB + 256);
    float4 bc1_n = *(const float4*)(g_dbl2 + (base_row)*NCOMB + 260);
    for (int t = 0; t < SEQ; t++) {
        float u = u_n, z = z_n, dtp0 = dtp_n;
        float4 bc0 = bc0_n, bc1 = bc1_n;
        if (t + 1 < SEQ) {
            size_t row1 = base_row + t + 1;
            u_n   = g_xz[row1*DX2 + d];
            z_n   = g_xz[row1*DX2 + DINNER + d];
            dtp_n = g_dbl2[row1*NCOMB + d];
            bc0_n = *(const float4*)(g_dbl2 + row1*NCOMB + 256);
            bc1_n = *(const float4*)(g_dbl2 + row1*NCOMB + 260);
        }
        float cv  = fmaf(up, w0, fmaf(u, w1, cb));
        float xc  = cv / (1.f + __expf(-cv));
        up = u;
        float dtp = dtp0 + bdt;
        float dt  = fmaxf(dtp, 0.f) + log1pf(__expf(-fabsf(dtp)));
        float dtxc = dt * xc;
        h0 = fmaf(h0, __expf(dt * A0), dtxc * bc0.x);
        h1 = fmaf(h1, __expf(dt * A1), dtxc * bc0.y);
        h2 = fmaf(h2, __expf(dt * A2), dtxc * bc0.z);
        h3 = fmaf(h3, __expf(dt * A3), dtxc * bc0.w);
        float y = h0*bc1.x + h1*bc1.y + h2*bc1.z + h3*bc1.w;
        y = fmaf(Dd, xc, y);
        float sz = z / (1.f + __expf(-z));
        g_y[(base_row + t) * DINNER + d] = y * sz;
    }
}

// ---------------- final ----------------
__global__ __launch_bounds__(256)
void k_final() {
    __shared__ float sW[15][CHUNK];
    const int cx = blockIdx.x;
    const int bg = blockIdx.y;
    const int k0 = cx * CHUNK;
    const int tid = threadIdx.x;
    for (int idx = tid; idx < 15*CHUNK; idx += 256) {
        int i = idx / CHUNK, k = idx - i*CHUNK;
        sW[i][k] = g_Whead2[(size_t)i*KHEAD + k0 + k];
    }
    __syncthreads();
    const int w = tid >> 5, lane = tid & 31;
    #pragma unroll
    for (int bi = 0; bi < 2; bi++) {
        int b = bg * 16 + w * 2 + bi;
        const float* yrow = g_y + (size_t)b * KHEAD + k0;
        #pragma unroll 1
        for (int i = 0; i < 15; i++) {
            float s = 0.f;
            #pragma unroll
            for (int k = lane; k < CHUNK; k += 32) s = fmaf(yrow[k], sW[i][k], s);
            #pragma unroll
            for (int o = 16; o > 0; o >>= 1) s += __shfl_xor_sync(0xffffffffu, s, o);
            if (lane == 0) atomicAdd(&g_acc[i*128 + b], s);
        }
    }
}

__global__ __launch_bounds__(256)
void k_sig(float* __restrict__ out) {
    int p = blockIdx.x * 256 + threadIdx.x;
    if (p >= 15*128) return;
    int b = p / 15, i = p - b*15;
    out[p] = 1.f / (1.f + expf(-(g_acc[i*128 + b] + g_bhead[i])));
}

// ---------------- launch ----------------
extern "C" void kernel_launch(void* const* d_in, const int* in_sizes, int n_in,
                              void* d_out, int out_size) {
    const float* x         = (const float*)d_in[0];
    const float* lin1_w    = (const float*)d_in[1];
    const float* lin1_b    = (const float*)d_in[2];
    const float* bn1_g     = (const float*)d_in[3];
    const float* bn1_b     = (const float*)d_in[4];
    const float* ln_g      = (const float*)d_in[5];
    const float* ln_b      = (const float*)d_in[6];
    const float* in_proj_w = (const float*)d_in[7];
    const float* conv_w    = (const float*)d_in[8];
    const float* conv_b    = (const float*)d_in[9];
    const float* x_proj_w  = (const float*)d_in[10];
    const float* dt_proj_w = (const float*)d_in[11];
    const float* dt_proj_b = (const float*)d_in[12];
    const float* A_log     = (const float*)d_in[13];
    const float* Dp        = (const float*)d_in[14];
    const float* out_proj_w= (const float*)d_in[15];
    const float* bn5_g     = (const float*)d_in[16];
    const float* bn5_b     = (const float*)d_in[17];
    const float* l5a_w     = (const float*)d_in[18];
    const float* l5a_b     = (const float*)d_in[19];
    const float* l5b_w     = (const float*)d_in[20];
    const float* l5b_b     = (const float*)d_in[21];
    const float* l5c_w     = (const float*)d_in[22];
    const float* l5c_b     = (const float*)d_in[23];
    const float* fc3_w     = (const float*)d_in[24];
    const float* fc3_b     = (const float*)d_in[25];

    float *p_xln, *p_xz, *p_dbl2, *p_Wcomb;
    cudaGetSymbolAddress((void**)&p_xln,   g_xln);
    cudaGetSymbolAddress((void**)&p_xz,    g_xz);
    cudaGetSymbolAddress((void**)&p_dbl2,  g_dbl2);
    cudaGetSymbolAddress((void**)&p_Wcomb, g_Wcomb);

    cudaFuncSetAttribute(k_mma,      cudaFuncAttributeMaxDynamicSharedMemorySize, SMEM_GEMM);
    cudaFuncSetAttribute(k_mma_conv, cudaFuncAttributeMaxDynamicSharedMemorySize, SMEM_GEMM);

    const int GY = MROWS / 128;   // 176

    // 0: front
    k_front<<<MROWS/8, 256>>>(x, lin1_w, lin1_b, bn1_g, bn1_b, ln_g, ln_b);
    // 1: wcomb
    k_wcomb<<<NCOMB, 256>>>(dt_proj_w, x_proj_w);
    // 2: in_proj  [M,256]@[512,256]^T
    k_mma<<<dim3(8, GY), 256, SMEM_GEMM>>>(p_xln, DMODEL, in_proj_w, p_xz, DX2, DMODEL);
    // 3: fused conv+silu + (dt_pre|B|C) GEMM   <-- profiled slot
    k_mma_conv<<<dim3(5, GY), 256, SMEM_GEMM>>>(conv_w, conv_b, p_Wcomb, p_dbl2, NCOMB, DINNER);
    // 4: t1
    k_t1<<<64, 256>>>(l5a_w, l5a_b, l5b_w, l5b_b);
    // 5: t2
    k_t2<<<16, 256>>>(l5c_w, l5c_b);
    // 6: Wc2 = Wc @ Wout
    k_wc2<<<16, 256>>>(out_proj_w);
    // 7: t3 -> Whead2 directly
    k_t3<<<dim3(SEQ, 15), 256>>>(fc3_w, bn5_g);
    // 8: bias (+ zero acc)
    k_bias<<<1, 512>>>(fc3_w, fc3_b, bn5_b);
    // 9: scan
    k_scan<<<dim3(BATCH, 2), 128>>>(A_log, Dp, dt_proj_b, conv_w, conv_b);
    // 10: folded head
    k_final<<<dim3(KHEAD/CHUNK, 8), 256>>>();
    // 11: sigmoid
    k_sig<<<(15*128 + 255)/256, 256>>>((float*)d_out);
}

// round 14
// speedup vs baseline: 1.1478x; 1.0600x over previous
#include <cuda_runtime.h>
#include <cuda_bf16.h>
#include <math.h>
#include <stdint.h>

#define BATCH 128
#define SEQ 176
#define DIN 20
#define DMODEL 256
#define DINNER 256
#define DX2 512
#define MROWS (BATCH*SEQ)   /* 22528 */
#define DSTATE 4
#define DTRANK 16
#define EPSF 1e-5f
#define NCOMB 264
#define KHEAD (SEQ*DMODEL)  /* 45056 */
#define CHUNK 352

// GEMM smem geometry (bf16 elements)
#define GSA 40
#define GSBK 40
#define OFF_AL 10240
#define OFF_BH 20480
#define OFF_BL 25600
#define BUFSZ  30720
#define SMEM_GEMM (2*BUFSZ)

// ---------------- scratch ----------------
__device__ __align__(16) float g_xln [MROWS*DMODEL];
__device__ __align__(16) float g_xz  [MROWS*DX2];
__device__ __align__(16) float g_xc  [MROWS*DINNER];
__device__ __align__(16) float g_dbl2[MROWS*NCOMB];
__device__ __align__(16) float g_y   [MROWS*DINNER];
__device__ __align__(16) float g_Wcomb[NCOMB*DMODEL];
__device__ __align__(16) float g_T1  [64*256];
__device__ __align__(16) float g_Wc  [16*256];
__device__ __align__(16) float g_Wc2 [16*256];
__device__ float g_bc1[64];
__device__ float g_bc2[16];
__device__ float g_Sc [16];
__device__ __align__(16) float g_Whead2[15*KHEAD];
__device__ float g_bhead[15];
__device__ float g_acc[15*128];

// ================= mma.sync helpers =================
__device__ __forceinline__ uint32_t smem_u32(const void* p) {
    uint32_t a;
    asm("{ .reg .u64 t; cvta.to.shared.u64 t, %1; cvt.u32.u64 %0, t; }" : "=r"(a) : "l"(p));
    return a;
}
__device__ __forceinline__ void ldsm_x4(uint32_t addr, uint32_t* r) {
    asm volatile("ldmatrix.sync.aligned.m8n8.x4.shared.b16 {%0,%1,%2,%3}, [%4];"
        : "=r"(r[0]),"=r"(r[1]),"=r"(r[2]),"=r"(r[3]) : "r"(addr));
}
__device__ __forceinline__ void mma_bf16(float* c, const uint32_t* a, const uint32_t* b) {
    asm volatile("mma.sync.aligned.m16n8k16.row.col.f32.bf16.bf16.f32 "
        "{%0,%1,%2,%3}, {%4,%5,%6,%7}, {%8,%9}, {%0,%1,%2,%3};"
        : "+f"(c[0]),"+f"(c[1]),"+f"(c[2]),"+f"(c[3])
        : "r"(a[0]),"r"(a[1]),"r"(a[2]),"r"(a[3]), "r"(b[0]),"r"(b[1]));
}
__device__ __forceinline__ float silu_f(float v) {
    return v / (1.f + __expf(-v));
}
__device__ __forceinline__ void split4(float4 v, uint2& hp, uint2& lp) {
    __nv_bfloat162 h01 = __floats2bfloat162_rn(v.x, v.y);
    __nv_bfloat162 h23 = __floats2bfloat162_rn(v.z, v.w);
    __nv_bfloat162 l01 = __floats2bfloat162_rn(v.x - __low2float(h01), v.y - __high2float(h01));
    __nv_bfloat162 l23 = __floats2bfloat162_rn(v.z - __low2float(h23), v.w - __high2float(h23));
    hp.x = *(uint32_t*)&h01; hp.y = *(uint32_t*)&h23;
    lp.x = *(uint32_t*)&l01; lp.y = *(uint32_t*)&l23;
}

// ---------------- GEMM core: 256 threads, 8 warps (4 wm x 2 wn), double-buffered ----------------
__global__ __launch_bounds__(256)
void k_mma(const float* __restrict__ A, int lda,
           const float* __restrict__ W,
           float* __restrict__ C, int N, int K) {
    extern __shared__ char sm_[];
    const int tid  = threadIdx.x;
    const int lane = tid & 31;
    const int wid  = tid >> 5;
    const int wm   = wid & 3;
    const int wn   = wid >> 2;
    const int row0 = blockIdx.y * 128;
    const int col0 = blockIdx.x * 64;
    float acc[2][4][4];
    #pragma unroll
    for (int a_ = 0; a_ < 2; a_++)
        #pragma unroll
        for (int b_ = 0; b_ < 4; b_++)
            #pragma unroll
            for (int c_ = 0; c_ < 4; c_++) acc[a_][b_][c_] = 0.f;
    float4 va[4], vb[2];
    auto ld = [&](int k0c) {
        #pragma unroll
        for (int u = 0; u < 4; u++) {
            int i = tid + u*256;
            int r = i >> 3, c4 = (i & 7) << 2;
            va[u] = *(const float4*)(A + (size_t)(row0 + r) * lda + k0c + c4);
        }
        #pragma unroll
        for (int u = 0; u < 2; u++) {
            int i = tid + u*256;
            int r = i >> 3, c4 = (i & 7) << 2;
            vb[u] = (col0 + r < N)
                  ? *(const float4*)(W + (size_t)(col0 + r) * K + k0c + c4)
                  : make_float4(0.f, 0.f, 0.f, 0.f);
        }
    };
    auto st = [&](int buf) {
        char* base = sm_ + buf * BUFSZ;
        __nv_bfloat16* Ah = (__nv_bfloat16*)(base);
        __nv_bfloat16* Al = (__nv_bfloat16*)(base + OFF_AL);
        __nv_bfloat16* Bh = (__nv_bfloat16*)(base + OFF_BH);
        __nv_bfloat16* Bl = (__nv_bfloat16*)(base + OFF_BL);
        #pragma unroll
        for (int u = 0; u < 4; u++) {
            int i = tid + u*256;
            int r = i >> 3, c4 = (i & 7) << 2;
            uint2 hp, lp; split4(va[u], hp, lp);
            *(uint2*)(Ah + r*GSA + c4) = hp;
            *(uint2*)(Al + r*GSA + c4) = lp;
        }
        #pragma unroll
        for (int u = 0; u < 2; u++) {
            int i = tid + u*256;
            int r = i >> 3, c4 = (i & 7) << 2;
            uint2 hp, lp; split4(vb[u], hp, lp);
            *(uint2*)(Bh + r*GSBK + c4) = hp;
            *(uint2*)(Bl + r*GSBK + c4) = lp;
        }
    };
    auto domma = [&](int buf) {
        char* base = sm_ + buf * BUFSZ;
        const __nv_bfloat16* Ah = (const __nv_bfloat16*)(base);
        const __nv_bfloat16* Al = (const __nv_bfloat16*)(base + OFF_AL);
        const __nv_bfloat16* Bh = (const __nv_bfloat16*)(base + OFF_BH);
        const __nv_bfloat16* Bl = (const __nv_bfloat16*)(base + OFF_BL);
        #pragma unroll
        for (int ks = 0; ks < 2; ks++) {
            const int kb = ks * 16;
            uint32_t ah[2][4], al[2][4];
            #pragma unroll
            for (int mi = 0; mi < 2; mi++) {
                int r  = wm*32 + mi*16 + (lane & 15);
                int kk = kb + ((lane & 16) ? 8 : 0);
                ldsm_x4(smem_u32(Ah + r*GSA + kk), ah[mi]);
                ldsm_x4(smem_u32(Al + r*GSA + kk), al[mi]);
            }
            uint32_t bh[4][2], bl[4][2];
            #pragma unroll
            for (int np = 0; np < 2; np++) {
                int nb = wn*32 + np*16;
                int tile = lane >> 3, rowj = lane & 7;
                int k_off = kb + (tile & 1) * 8;
                int n_off = nb + ((tile >> 1) & 1) * 8;
                uint32_t r4[4];
                ldsm_x4(smem_u32(Bh + (n_off + rowj)*GSBK + k_off), r4);
                bh[np*2][0]=r4[0]; bh[np*2][1]=r4[1];
                bh[np*2+1][0]=r4[2]; bh[np*2+1][1]=r4[3];
                ldsm_x4(smem_u32(Bl + (n_off + rowj)*GSBK + k_off), r4);
                bl[np*2][0]=r4[0]; bl[np*2][1]=r4[1];
                bl[np*2+1][0]=r4[2]; bl[np*2+1][1]=r4[3];
            }
            #pragma unroll
            for (int mi = 0; mi < 2; mi++)
                #pragma unroll
                for (int ni = 0; ni < 4; ni++) {
                    mma_bf16(acc[mi][ni], ah[mi], bh[ni]);
                    mma_bf16(acc[mi][ni], ah[mi], bl[ni]);
                    mma_bf16(acc[mi][ni], al[mi], bh[ni]);
                }
        }
    };
    const int nch = K >> 5;
    ld(0);
    st(0);
    __syncthreads();
    for (int ci = 0; ci < nch; ci++) {
        int cur = ci & 1;
        if (ci + 1 < nch) ld((ci + 1) << 5);
        domma(cur);
        if (ci + 1 < nch) st(cur ^ 1);
        __syncthreads();
    }
    #pragma unroll
    for (int mi = 0; mi < 2; mi++) {
        #pragma unroll
        for (int ni = 0; ni < 4; ni++) {
            int r = row0 + wm*32 + mi*16 + (lane >> 2);
            int c = col0 + wn*32 + ni*8 + (lane & 3) * 2;
            #pragma unroll
            for (int half = 0; half < 2; half++) {
                int rr = r + half * 8;
                float v0 = acc[mi][ni][half*2 + 0];
                float v1 = acc[mi][ni][half*2 + 1];
                float* crow = C + (size_t)rr * N;
                if (c + 1 < N)      *(float2*)(crow + c) = make_float2(v0, v1);
                else if (c < N)     crow[c] = v0;
            }
        }
    }
}

// ---------------- standalone conv+SiLU (vectorized, writes g_xc once) ----------------
__global__ __launch_bounds__(256)
void k_conv(const float* __restrict__ convw, const float* __restrict__ convb) {
    int i = blockIdx.x * 256 + threadIdx.x;     // over MROWS*64 float4 groups
    if (i >= MROWS * 64) return;
    int row = i >> 6;
    int k   = (i & 63) << 2;
    const float* b1 = g_xz + (size_t)row * DX2 + k;
    float4 u1 = *(const float4*)b1;
    float4 u0 = ((row % SEQ) == 0) ? make_float4(0.f,0.f,0.f,0.f)
                                   : *(const float4*)(b1 - DX2);
    float4 cw0 = __ldg((const float4*)(convw + 2*k));
    float4 cw1 = __ldg((const float4*)(convw + 2*k + 4));
    float4 cb4 = __ldg((const float4*)(convb + k));
    float4 o;
    o.x = silu_f(fmaf(u0.x, cw0.x, fmaf(u1.x, cw0.y, cb4.x)));
    o.y = silu_f(fmaf(u0.y, cw0.z, fmaf(u1.y, cw0.w, cb4.y)));
    o.z = silu_f(fmaf(u0.z, cw1.x, fmaf(u1.z, cw1.y, cb4.z)));
    o.w = silu_f(fmaf(u0.w, cw1.z, fmaf(u1.w, cw1.w, cb4.w)));
    *(float4*)(g_xc + (size_t)row * DINNER + k) = o;
}

// ---------------- precompute kernels ----------------
__global__ __launch_bounds__(256)
void k_wcomb(const float* __restrict__ dtw, const float* __restrict__ xpw) {
    int r = blockIdx.x, c = threadIdx.x;
    float v;
    if (r < 256) {
        v = 0.f;
        #pragma unroll
        for (int j = 0; j < 16; j++) v = fmaf(dtw[r*16 + j], xpw[j*256 + c], v);
    } else {
        v = xpw[(r - 256 + 16)*256 + c];
    }
    g_Wcomb[r*256 + c] = v;
}

__global__ __launch_bounds__(256)
void k_t1(const float* __restrict__ l5aw, const float* __restrict__ l5ab,
          const float* __restrict__ l5bw, const float* __restrict__ l5bb) {
    int r = blockIdx.x, c = threadIdx.x;
    __shared__ float wr[128];
    if (c < 128) wr[c] = l5bw[r*128 + c];
    __syncthreads();
    float v = 0.f;
    for (int j = 0; j < 128; j++) v = fmaf(wr[j], l5aw[j*256 + c], v);
    g_T1[r*256 + c] = v;
    if (c == 0) {
        float b = l5bb[r];
        for (int j = 0; j < 128; j++) b = fmaf(wr[j], l5ab[j], b);
        g_bc1[r] = b;
    }
}

__global__ __launch_bounds__(256)
void k_t2(const float* __restrict__ l5cw, const float* __restrict__ l5cb) {
    int r = blockIdx.x, c = threadIdx.x;
    __shared__ float wr[64];
    __shared__ float red[8];
    if (c < 64) wr[c] = l5cw[r*64 + c];
    __syncthreads();
    float v = 0.f;
    for (int j = 0; j < 64; j++) v = fmaf(wr[j], g_T1[j*256 + c], v);
    g_Wc[r*256 + c] = v;
    float s = v;
    #pragma unroll
    for (int o = 16; o > 0; o >>= 1) s += __shfl_xor_sync(0xffffffffu, s, o);
    if ((c & 31) == 0) red[c >> 5] = s;
    __syncthreads();
    if (c == 0) {
        float t = 0.f;
        for (int j = 0; j < 8; j++) t += red[j];
        g_Sc[r] = t;
        float b = l5cb[r];
        for (int j = 0; j < 64; j++) b = fmaf(wr[j], g_bc1[j], b);
        g_bc2[r] = b;
    }
}

__global__ __launch_bounds__(256)
void k_wc2(const float* __restrict__ outw) {
    int o = blockIdx.x, j = threadIdx.x;
    __shared__ float wcs[256];
    wcs[j] = g_Wc[o*256 + j];
    __syncthreads();
    float v = 0.f;
    for (int c = 0; c < 256; c++) v = fmaf(wcs[c], outw[c*256 + j], v);
    g_Wc2[o*256 + j] = v;
}

__global__ __launch_bounds__(256)
void k_t3(const float* __restrict__ fc3w, const float* __restrict__ bn5g) {
    int l = blockIdx.x, i = blockIdx.y, c = threadIdx.x;
    __shared__ float f[16];
    if (c < 16) f[c] = fc3w[i*2816 + l*16 + c];
    __syncthreads();
    float v = 0.f;
    #pragma unroll
    for (int o = 0; o < 16; o++) v = fmaf(f[o], g_Wc2[o*256 + c], v);
    float sl = bn5g[l] * rsqrtf(1.0f + EPSF);
    g_Whead2[((size_t)i*SEQ + l)*256 + c] = v * sl;
}

__global__ __launch_bounds__(512)
void k_bias(const float* __restrict__ fc3w, const float* __restrict__ fc3b,
            const float* __restrict__ bn5b) {
    int w = threadIdx.x >> 5, lane = threadIdx.x & 31;
    for (int p = threadIdx.x; p < 15*128; p += 512) g_acc[p] = 0.f;
    if (w >= 15) return;
    float s = 0.f;
    for (int idx = lane; idx < 2816; idx += 32) {
        int l = idx >> 4, o = idx & 15;
        s = fmaf(fc3w[w*2816 + idx], g_bc2[o] + bn5b[l]*g_Sc[o], s);
    }
    #pragma unroll
    for (int o = 16; o > 0; o >>= 1) s += __shfl_xor_sync(0xffffffffu, s, o);
    if (lane == 0) g_bhead[w] = fc3b[w] + s;
}

// ---------------- front: warp-per-row ----------------
__global__ __launch_bounds__(256)
void k_front(const float* __restrict__ x,
             const float* __restrict__ w, const float* __restrict__ b,
             const float* __restrict__ bn_g, const float* __restrict__ bn_b,
             const float* __restrict__ ln_g, const float* __restrict__ ln_b) {
    const int warp = threadIdx.x >> 5, lane = threadIdx.x & 31;
    const int row  = blockIdx.x * 8 + warp;
    const int l    = row % SEQ;
    float xv[DIN];
    #pragma unroll
    for (int k = 0; k < DIN; k++) xv[k] = __ldg(x + row*DIN + k);
    const float scale = __ldg(bn_g + l) * rsqrtf(1.0f + EPSF);
    const float shift = __ldg(bn_b + l);
    float v[8];
    float s = 0.f;
    #pragma unroll
    for (int j = 0; j < 8; j++) {
        int c = lane + 32*j;
        float acc = __ldg(b + c);
        const float* wc = w + c*DIN;
        #pragma unroll
        for (int k = 0; k < DIN; k++) acc = fmaf(xv[k], __ldg(wc + k), acc);
        acc = acc * scale + shift;
        acc = acc >= 0.f ? acc : 0.01f * acc;
        v[j] = acc;
        s += acc;
    }
    #pragma unroll
    for (int o = 16; o > 0; o >>= 1) s += __shfl_xor_sync(0xffffffffu, s, o);
    const float mu = s * (1.0f/256.0f);
    float q = 0.f;
    #pragma unroll
    for (int j = 0; j < 8; j++) { float d = v[j] - mu; q += d*d; }
    #pragma unroll
    for (int o = 16; o > 0; o >>= 1) q += __shfl_xor_sync(0xffffffffu, q, o);
    const float rstd = rsqrtf(q * (1.0f/256.0f) + EPSF);
    #pragma unroll
    for (int j = 0; j < 8; j++) {
        int c = lane + 32*j;
        g_xln[row*DMODEL + c] = (v[j] - mu) * rstd * __ldg(ln_g + c) + __ldg(ln_b + c);
    }
}

// ---------------- selective scan (conv+silu + softplus inline, prefetched) ----------------
__global__ __launch_bounds__(128)
void k_scan(const float* __restrict__ A_log, const float* __restrict__ Dp,
            const float* __restrict__ dtb,
            const float* __restrict__ convw, const float* __restrict__ convb) {
    int b = blockIdx.x;
    int d = blockIdx.y * 128 + threadIdx.x;
    float A0 = -expf(A_log[d*4+0]);
    float A1 = -expf(A_log[d*4+1]);
    float A2 = -expf(A_log[d*4+2]);
    float A3 = -expf(A_log[d*4+3]);
    float Dd = Dp[d];
    float bdt = dtb[d];
    float w0 = convw[2*d], w1 = convw[2*d+1], cb = convb[d];
    float h0 = 0.f, h1 = 0.f, h2 = 0.f, h3 = 0.f;
    float up = 0.f;
    const size_t base_row = (size_t)b * SEQ;
    float u_n   = g_xz[(base_row)*DX2 + d];
    float z_n   = g_xz[(base_row)*DX2 + DINNER + d];
    float dtp_n = g_dbl2[(base_row)*NCOMB + d];
    float4 bc0_n = *(const float4*)(g_dbl2 + (base_row)*NCOMB + 256);
    float4 bc1_n = *(const float4*)(g_dbl2 + (base_row)*NCOMB + 260);
    for (int t = 0; t < SEQ; t++) {
        float u = u_n, z = z_n, dtp0 = dtp_n;
        float4 bc0 = bc0_n, bc1 = bc1_n;
        if (t + 1 < SEQ) {
            size_t row1 = base_row + t + 1;
            u_n   = g_xz[row1*DX2 + d];
            z_n   = g_xz[row1*DX2 + DINNER + d];
            dtp_n = g_dbl2[row1*NCOMB + d];
            bc0_n = *(const float4*)(g_dbl2 + row1*NCOMB + 256);
            bc1_n = *(const float4*)(g_dbl2 + row1*NCOMB + 260);
        }
        float cv  = fmaf(up, w0, fmaf(u, w1, cb));
        float xc  = cv / (1.f + __expf(-cv));
        up = u;
        float dtp = dtp0 + bdt;
        float dt  = fmaxf(dtp, 0.f) + log1pf(__expf(-fabsf(dtp)));
        float dtxc = dt * xc;
        h0 = fmaf(h0, __expf(dt * A0), dtxc * bc0.x);
        h1 = fmaf(h1, __expf(dt * A1), dtxc * bc0.y);
        h2 = fmaf(h2, __expf(dt * A2), dtxc * bc0.z);
        h3 = fmaf(h3, __expf(dt * A3), dtxc * bc0.w);
        float y = h0*bc1.x + h1*bc1.y + h2*bc1.z + h3*bc1.w;
        y = fmaf(Dd, xc, y);
        float sz = z / (1.f + __expf(-z));
        g_y[(base_row + t) * DINNER + d] = y * sz;
    }
}

// ---------------- final ----------------
__global__ __launch_bounds__(256)
void k_final() {
    __shared__ float sW[15][CHUNK];
    const int cx = blockIdx.x;
    const int bg = blockIdx.y;
    const int k0 = cx * CHUNK;
    const int tid = threadIdx.x;
    for (int idx = tid; idx < 15*CHUNK; idx += 256) {
        int i = idx / CHUNK, k = idx - i*CHUNK;
        sW[i][k] = g_Whead2[(size_t)i*KHEAD + k0 + k];
    }
    __syncthreads();
    const int w = tid >> 5, lane = tid & 31;
    #pragma unroll
    for (int bi = 0; bi < 2; bi++) {
        int b = bg * 16 + w * 2 + bi;
        const float* yrow = g_y + (size_t)b * KHEAD + k0;
        #pragma unroll 1
        for (int i = 0; i < 15; i++) {
            float s = 0.f;
            #pragma unroll
            for (int k = lane; k < CHUNK; k += 32) s = fmaf(yrow[k], sW[i][k], s);
            #pragma unroll
            for (int o = 16; o > 0; o >>= 1) s += __shfl_xor_sync(0xffffffffu, s, o);
            if (lane == 0) atomicAdd(&g_acc[i*128 + b], s);
        }
    }
}

__global__ __launch_bounds__(256)
void k_sig(float* __restrict__ out) {
    int p = blockIdx.x * 256 + threadIdx.x;
    if (p >= 15*128) return;
    int b = p / 15, i = p - b*15;
    out[p] = 1.f / (1.f + expf(-(g_acc[i*128 + b] + g_bhead[i])));
}

// ---------------- launch ----------------
extern "C" void kernel_launch(void* const* d_in, const int* in_sizes, int n_in,
                              void* d_out, int out_size) {
    const float* x         = (const float*)d_in[0];
    const float* lin1_w    = (const float*)d_in[1];
    const float* lin1_b    = (const float*)d_in[2];
    const float* bn1_g     = (const float*)d_in[3];
    const float* bn1_b     = (const float*)d_in[4];
    const float* ln_g      = (const float*)d_in[5];
    const float* ln_b      = (const float*)d_in[6];
    const float* in_proj_w = (const float*)d_in[7];
    const float* conv_w    = (const float*)d_in[8];
    const float* conv_b    = (const float*)d_in[9];
    const float* x_proj_w  = (const float*)d_in[10];
    const float* dt_proj_w = (const float*)d_in[11];
    const float* dt_proj_b = (const float*)d_in[12];
    const float* A_log     = (const float*)d_in[13];
    const float* Dp        = (const float*)d_in[14];
    const float* out_proj_w= (const float*)d_in[15];
    const float* bn5_g     = (const float*)d_in[16];
    const float* bn5_b     = (const float*)d_in[17];
    const float* l5a_w     = (const float*)d_in[18];
    const float* l5a_b     = (const float*)d_in[19];
    const float* l5b_w     = (const float*)d_in[20];
    const float* l5b_b     = (const float*)d_in[21];
    const float* l5c_w     = (const float*)d_in[22];
    const float* l5c_b     = (const float*)d_in[23];
    const float* fc3_w     = (const float*)d_in[24];
    const float* fc3_b     = (const float*)d_in[25];

    float *p_xln, *p_xz, *p_xc, *p_dbl2, *p_Wcomb;
    cudaGetSymbolAddress((void**)&p_xln,   g_xln);
    cudaGetSymbolAddress((void**)&p_xz,    g_xz);
    cudaGetSymbolAddress((void**)&p_xc,    g_xc);
    cudaGetSymbolAddress((void**)&p_dbl2,  g_dbl2);
    cudaGetSymbolAddress((void**)&p_Wcomb, g_Wcomb);

    cudaFuncSetAttribute(k_mma, cudaFuncAttributeMaxDynamicSharedMemorySize, SMEM_GEMM);

    const int GY = MROWS / 128;   // 176

    // 0: front
    k_front<<<MROWS/8, 256>>>(x, lin1_w, lin1_b, bn1_g, bn1_b, ln_g, ln_b);
    // 1: wcomb
    k_wcomb<<<NCOMB, 256>>>(dt_proj_w, x_proj_w);
    // 2: in_proj  [M,256]@[512,256]^T
    k_mma<<<dim3(8, GY), 256, SMEM_GEMM>>>(p_xln, DMODEL, in_proj_w, p_xz, DX2, DMODEL);
    // 3: conv+silu elementwise  <-- profiled slot (expect ~12-15us, DRAM-bound)
    k_conv<<<(MROWS*64 + 255)/256, 256>>>(conv_w, conv_b);
    // 4: comb GEMM: xc @ Wcomb^T -> [M,264]
    k_mma<<<dim3(5, GY), 256, SMEM_GEMM>>>(p_xc, DINNER, p_Wcomb, p_dbl2, NCOMB, DINNER);
    // 5: t1
    k_t1<<<64, 256>>>(l5a_w, l5a_b, l5b_w, l5b_b);
    // 6: t2
    k_t2<<<16, 256>>>(l5c_w, l5c_b);
    // 7: Wc2 = Wc @ Wout
    k_wc2<<<16, 256>>>(out_proj_w);
    // 8: t3 -> Whead2
    k_t3<<<dim3(SEQ, 15), 256>>>(fc3_w, bn5_g);
    // 9: bias (+ zero acc)
    k_bias<<<1, 512>>>(fc3_w, fc3_b, bn5_b);
    // 10: scan
    k_scan<<<dim3(BATCH, 2), 128>>>(A_log, Dp, dt_proj_b, conv_w, conv_b);
    // 11: folded head
    k_final<<<dim3(KHEAD/CHUNK, 8), 256>>>();
    // 12: sigmoid
    k_sig<<<(15*128 + 255)/256, 256>>>((float*)d_out);
}

// round 15
// speedup vs baseline: 1.1653x; 1.0152x over previous
#include <cuda_runtime.h>
#include <cuda_bf16.h>
#include <math.h>
#include <stdint.h>

#define BATCH 128
#define SEQ 176
#define DIN 20
#define DMODEL 256
#define DINNER 256
#define DX2 512
#define MROWS (BATCH*SEQ)   /* 22528 */
#define DSTATE 4
#define DTRANK 16
#define EPSF 1e-5f
#define NCOMB 264
#define KHEAD (SEQ*DMODEL)  /* 45056 */
#define CHUNK2 256
#define NCHUNK (KHEAD/CHUNK2)   /* 176 */

// GEMM smem geometry (bf16 elements)
#define GSA 40
#define GSBK 40
#define OFF_AL 10240
#define OFF_BH 20480
#define OFF_BL 25600
#define BUFSZ  30720
#define SMEM_GEMM (2*BUFSZ)

// ---------------- scratch ----------------
__device__ __align__(16) float g_xln [MROWS*DMODEL];
__device__ __align__(16) float g_xz  [MROWS*DX2];
__device__ __align__(16) float g_xc  [MROWS*DINNER];
__device__ __align__(16) float g_dbl2[MROWS*NCOMB];
__device__ __align__(16) float g_y   [MROWS*DINNER];
__device__ __align__(16) float g_Wcomb[NCOMB*DMODEL];
__device__ __align__(16) float g_T1  [64*256];
__device__ __align__(16) float g_T1W [64*256];
__device__ __align__(16) float g_Wc2 [16*256];
__device__ float g_bc1[64];
__device__ float g_rs1[64];
__device__ __align__(16) float g_Whead2[15*KHEAD];
__device__ float g_bhead[15];
__device__ float g_acc[15*128];
__device__ int   g_done;

// ================= mma.sync helpers =================
__device__ __forceinline__ uint32_t smem_u32(const void* p) {
    uint32_t a;
    asm("{ .reg .u64 t; cvta.to.shared.u64 t, %1; cvt.u32.u64 %0, t; }" : "=r"(a) : "l"(p));
    return a;
}
__device__ __forceinline__ void ldsm_x4(uint32_t addr, uint32_t* r) {
    asm volatile("ldmatrix.sync.aligned.m8n8.x4.shared.b16 {%0,%1,%2,%3}, [%4];"
        : "=r"(r[0]),"=r"(r[1]),"=r"(r[2]),"=r"(r[3]) : "r"(addr));
}
__device__ __forceinline__ void mma_bf16(float* c, const uint32_t* a, const uint32_t* b) {
    asm volatile("mma.sync.aligned.m16n8k16.row.col.f32.bf16.bf16.f32 "
        "{%0,%1,%2,%3}, {%4,%5,%6,%7}, {%8,%9}, {%0,%1,%2,%3};"
        : "+f"(c[0]),"+f"(c[1]),"+f"(c[2]),"+f"(c[3])
        : "r"(a[0]),"r"(a[1]),"r"(a[2]),"r"(a[3]), "r"(b[0]),"r"(b[1]));
}
__device__ __forceinline__ float silu_f(float v) {
    return v / (1.f + __expf(-v));
}
__device__ __forceinline__ void split4(float4 v, uint2& hp, uint2& lp) {
    __nv_bfloat162 h01 = __floats2bfloat162_rn(v.x, v.y);
    __nv_bfloat162 h23 = __floats2bfloat162_rn(v.z, v.w);
    __nv_bfloat162 l01 = __floats2bfloat162_rn(v.x - __low2float(h01), v.y - __high2float(h01));
    __nv_bfloat162 l23 = __floats2bfloat162_rn(v.z - __low2float(h23), v.w - __high2float(h23));
    hp.x = *(uint32_t*)&h01; hp.y = *(uint32_t*)&h23;
    lp.x = *(uint32_t*)&l01; lp.y = *(uint32_t*)&l23;
}

// ---------------- GEMM: 256 threads, 8 warps (4wm x 2wn), double-buffered ----------------
__global__ __launch_bounds__(256)
void k_mma(const float* __restrict__ A, int lda,
           const float* __restrict__ W,
           float* __restrict__ C, int N, int K) {
    extern __shared__ char sm_[];
    const int tid  = threadIdx.x;
    const int lane = tid & 31;
    const int wid  = tid >> 5;
    const int wm   = wid & 3;
    const int wn   = wid >> 2;
    const int row0 = blockIdx.y * 128;
    const int col0 = blockIdx.x * 64;
    float acc[2][4][4];
    #pragma unroll
    for (int a_ = 0; a_ < 2; a_++)
        #pragma unroll
        for (int b_ = 0; b_ < 4; b_++)
            #pragma unroll
            for (int c_ = 0; c_ < 4; c_++) acc[a_][b_][c_] = 0.f;
    float4 va[4], vb[2];
    auto ld = [&](int k0c) {
        #pragma unroll
        for (int u = 0; u < 4; u++) {
            int i = tid + u*256;
            int r = i >> 3, c4 = (i & 7) << 2;
            va[u] = *(const float4*)(A + (size_t)(row0 + r) * lda + k0c + c4);
        }
        #pragma unroll
        for (int u = 0; u < 2; u++) {
            int i = tid + u*256;
            int r = i >> 3, c4 = (i & 7) << 2;
            vb[u] = (col0 + r < N)
                  ? *(const float4*)(W + (size_t)(col0 + r) * K + k0c + c4)
                  : make_float4(0.f, 0.f, 0.f, 0.f);
        }
    };
    auto st = [&](int buf) {
        char* base = sm_ + buf * BUFSZ;
        __nv_bfloat16* Ah = (__nv_bfloat16*)(base);
        __nv_bfloat16* Al = (__nv_bfloat16*)(base + OFF_AL);
        __nv_bfloat16* Bh = (__nv_bfloat16*)(base + OFF_BH);
        __nv_bfloat16* Bl = (__nv_bfloat16*)(base + OFF_BL);
        #pragma unroll
        for (int u = 0; u < 4; u++) {
            int i = tid + u*256;
            int r = i >> 3, c4 = (i & 7) << 2;
            uint2 hp, lp; split4(va[u], hp, lp);
            *(uint2*)(Ah + r*GSA + c4) = hp;
            *(uint2*)(Al + r*GSA + c4) = lp;
        }
        #pragma unroll
        for (int u = 0; u < 2; u++) {
            int i = tid + u*256;
            int r = i >> 3, c4 = (i & 7) << 2;
            uint2 hp, lp; split4(vb[u], hp, lp);
            *(uint2*)(Bh + r*GSBK + c4) = hp;
            *(uint2*)(Bl + r*GSBK + c4) = lp;
        }
    };
    auto domma = [&](int buf) {
        char* base = sm_ + buf * BUFSZ;
        const __nv_bfloat16* Ah = (const __nv_bfloat16*)(base);
        const __nv_bfloat16* Al = (const __nv_bfloat16*)(base + OFF_AL);
        const __nv_bfloat16* Bh = (const __nv_bfloat16*)(base + OFF_BH);
        const __nv_bfloat16* Bl = (const __nv_bfloat16*)(base + OFF_BL);
        #pragma unroll
        for (int ks = 0; ks < 2; ks++) {
            const int kb = ks * 16;
            uint32_t ah[2][4], al[2][4];
            #pragma unroll
            for (int mi = 0; mi < 2; mi++) {
                int r  = wm*32 + mi*16 + (lane & 15);
                int kk = kb + ((lane & 16) ? 8 : 0);
                ldsm_x4(smem_u32(Ah + r*GSA + kk), ah[mi]);
                ldsm_x4(smem_u32(Al + r*GSA + kk), al[mi]);
            }
            uint32_t bh[4][2], bl[4][2];
            #pragma unroll
            for (int np = 0; np < 2; np++) {
                int nb = wn*32 + np*16;
                int tile = lane >> 3, rowj = lane & 7;
                int k_off = kb + (tile & 1) * 8;
                int n_off = nb + ((tile >> 1) & 1) * 8;
                uint32_t r4[4];
                ldsm_x4(smem_u32(Bh + (n_off + rowj)*GSBK + k_off), r4);
                bh[np*2][0]=r4[0]; bh[np*2][1]=r4[1];
                bh[np*2+1][0]=r4[2]; bh[np*2+1][1]=r4[3];
                ldsm_x4(smem_u32(Bl + (n_off + rowj)*GSBK + k_off), r4);
                bl[np*2][0]=r4[0]; bl[np*2][1]=r4[1];
                bl[np*2+1][0]=r4[2]; bl[np*2+1][1]=r4[3];
            }
            #pragma unroll
            for (int mi = 0; mi < 2; mi++)
                #pragma unroll
                for (int ni = 0; ni < 4; ni++) {
                    mma_bf16(acc[mi][ni], ah[mi], bh[ni]);
                    mma_bf16(acc[mi][ni], ah[mi], bl[ni]);
                    mma_bf16(acc[mi][ni], al[mi], bh[ni]);
                }
        }
    };
    const int nch = K >> 5;
    ld(0);
    st(0);
    __syncthreads();
    for (int ci = 0; ci < nch; ci++) {
        int cur = ci & 1;
        if (ci + 1 < nch) ld((ci + 1) << 5);
        domma(cur);
        if (ci + 1 < nch) st(cur ^ 1);
        __syncthreads();
    }
    #pragma unroll
    for (int mi = 0; mi < 2; mi++) {
        #pragma unroll
        for (int ni = 0; ni < 4; ni++) {
            int r = row0 + wm*32 + mi*16 + (lane >> 2);
            int c = col0 + wn*32 + ni*8 + (lane & 3) * 2;
            #pragma unroll
            for (int half = 0; half < 2; half++) {
                int rr = r + half * 8;
                float v0 = acc[mi][ni][half*2 + 0];
                float v1 = acc[mi][ni][half*2 + 1];
                float* crow = C + (size_t)rr * N;
                if (c + 1 < N)      *(float2*)(crow + c) = make_float2(v0, v1);
                else if (c < N)     crow[c] = v0;
            }
        }
    }
}

// ---------------- standalone conv+SiLU ----------------
__global__ __launch_bounds__(256)
void k_conv(const float* __restrict__ convw, const float* __restrict__ convb) {
    int i = blockIdx.x * 256 + threadIdx.x;
    if (i >= MROWS * 64) return;
    int row = i >> 6;
    int k   = (i & 63) << 2;
    const float* b1 = g_xz + (size_t)row * DX2 + k;
    float4 u1 = *(const float4*)b1;
    float4 u0 = ((row % SEQ) == 0) ? make_float4(0.f,0.f,0.f,0.f)
                                   : *(const float4*)(b1 - DX2);
    float4 cw0 = __ldg((const float4*)(convw + 2*k));
    float4 cw1 = __ldg((const float4*)(convw + 2*k + 4));
    float4 cb4 = __ldg((const float4*)(convb + k));
    float4 o;
    o.x = silu_f(fmaf(u0.x, cw0.x, fmaf(u1.x, cw0.y, cb4.x)));
    o.y = silu_f(fmaf(u0.y, cw0.z, fmaf(u1.y, cw0.w, cb4.y)));
    o.z = silu_f(fmaf(u0.z, cw1.x, fmaf(u1.z, cw1.y, cb4.z)));
    o.w = silu_f(fmaf(u0.w, cw1.z, fmaf(u1.w, cw1.w, cb4.w)));
    *(float4*)(g_xc + (size_t)row * DINNER + k) = o;
}

// ---------------- pre1: wcomb (blocks 0..263) + t1/bc1/rs1 (blocks 264..327) ----------------
__global__ __launch_bounds__(256)
void k_pre1(const float* __restrict__ dtw, const float* __restrict__ xpw,
            const float* __restrict__ l5aw, const float* __restrict__ l5ab,
            const float* __restrict__ l5bw, const float* __restrict__ l5bb) {
    int b = blockIdx.x, c = threadIdx.x;
    if (b < NCOMB) {
        float v;
        if (b < 256) {
            v = 0.f;
            #pragma unroll
            for (int j = 0; j < 16; j++) v = fmaf(dtw[b*16 + j], xpw[j*256 + c], v);
        } else {
            v = xpw[(b - 256 + 16)*256 + c];
        }
        g_Wcomb[b*256 + c] = v;
        return;
    }
    int r = b - NCOMB;   // 0..63
    __shared__ float wr[128];
    __shared__ float red[8];
    if (c < 128) wr[c] = l5bw[r*128 + c];
    __syncthreads();
    float v = 0.f;
    for (int j = 0; j < 128; j++) v = fmaf(wr[j], l5aw[j*256 + c], v);
    g_T1[r*256 + c] = v;
    float s = v;
    #pragma unroll
    for (int o = 16; o > 0; o >>= 1) s += __shfl_xor_sync(0xffffffffu, s, o);
    if ((c & 31) == 0) red[c >> 5] = s;
    __syncthreads();
    if (c == 0) {
        float t = 0.f;
        for (int j = 0; j < 8; j++) t += red[j];
        g_rs1[r] = t;
        float bb = l5bb[r];
        for (int j = 0; j < 128; j++) bb = fmaf(wr[j], l5ab[j], bb);
        g_bc1[r] = bb;
    }
}

// ---------------- t1w: T1W[r,j] = sum_c T1[r,c] * Wout[c,j] ----------------
__global__ __launch_bounds__(256)
void k_t1w(const float* __restrict__ outw) {
    int r = blockIdx.x, j = threadIdx.x;
    __shared__ float s[256];
    s[j] = g_T1[r*256 + j];
    __syncthreads();
    float v = 0.f;
    for (int c = 0; c < 256; c++) v = fmaf(s[c], outw[c*256 + j], v);
    g_T1W[r*256 + j] = v;
}

// ---------------- wc2b: blocks 0..15 -> Wc2 rows; block 16 -> bias + zero acc/done ----------------
__global__ __launch_bounds__(256)
void k_wc2b(const float* __restrict__ l5cw, const float* __restrict__ l5cb,
            const float* __restrict__ fc3w, const float* __restrict__ fc3b,
            const float* __restrict__ bn5b) {
    int b = blockIdx.x, tid = threadIdx.x;
    if (b < 16) {
        __shared__ float wr[64];
        if (tid < 64) wr[tid] = l5cw[b*64 + tid];
        __syncthreads();
        float v = 0.f;
        for (int r = 0; r < 64; r++) v = fmaf(wr[r], g_T1W[r*256 + tid], v);
        g_Wc2[b*256 + tid] = v;
        return;
    }
    // bias block
    __shared__ float bc2s[16], scs[16];
    for (int p = tid; p < 15*128; p += 256) g_acc[p] = 0.f;
    if (tid == 0) g_done = 0;
    if (tid < 16) {
        float bb = l5cb[tid], sc = 0.f;
        for (int r = 0; r < 64; r++) {
            float w = l5cw[tid*64 + r];
            bb = fmaf(w, g_bc1[r], bb);
            sc = fmaf(w, g_rs1[r], sc);
        }
        bc2s[tid] = bb;
        scs[tid]  = sc;
    }
    __syncthreads();
    int wid = tid >> 5, lane = tid & 31;
    for (int i = wid; i < 15; i += 8) {
        float s = 0.f;
        for (int idx = lane; idx < 2816; idx += 32) {
            int l = idx >> 4, o = idx & 15;
            s = fmaf(fc3w[i*2816 + idx], bc2s[o] + bn5b[l]*scs[o], s);
        }
        #pragma unroll
        for (int o = 16; o > 0; o >>= 1) s += __shfl_xor_sync(0xffffffffu, s, o);
        if (lane == 0) g_bhead[i] = fc3b[i] + s;
    }
}

// ---------------- t3: Whead2[i,l,c] = s_l * sum_o fc3_w[i,l*16+o] * Wc2[o,c] ----------------
__global__ __launch_bounds__(256)
void k_t3(const float* __restrict__ fc3w, const float* __restrict__ bn5g) {
    int l = blockIdx.x, i = blockIdx.y, c = threadIdx.x;
    __shared__ float f[16];
    if (c < 16) f[c] = fc3w[i*2816 + l*16 + c];
    __syncthreads();
    float v = 0.f;
    #pragma unroll
    for (int o = 0; o < 16; o++) v = fmaf(f[o], g_Wc2[o*256 + c], v);
    float sl = bn5g[l] * rsqrtf(1.0f + EPSF);
    g_Whead2[((size_t)i*SEQ + l)*256 + c] = v * sl;
}

// ---------------- front: warp-per-row, weights staged in smem ----------------
__global__ __launch_bounds__(256)
void k_front(const float* __restrict__ x,
             const float* __restrict__ w, const float* __restrict__ b,
             const float* __restrict__ bn_g, const float* __restrict__ bn_b,
             const float* __restrict__ ln_g, const float* __restrict__ ln_b) {
    __shared__ float ws[256*21];
    const int tid = threadIdx.x;
    for (int idx = tid; idx < 256*DIN; idx += 256) {
        int c = idx / DIN, k = idx - c*DIN;
        ws[c*21 + k] = w[idx];
    }
    __syncthreads();
    const int warp = tid >> 5, lane = tid & 31;
    const int row  = blockIdx.x * 8 + warp;
    const int l    = row % SEQ;
    float xv[DIN];
    #pragma unroll
    for (int k = 0; k < DIN; k++) xv[k] = __ldg(x + row*DIN + k);
    const float scale = __ldg(bn_g + l) * rsqrtf(1.0f + EPSF);
    const float shift = __ldg(bn_b + l);
    float v[8];
    float s = 0.f;
    #pragma unroll
    for (int j = 0; j < 8; j++) {
        int c = lane + 32*j;
        float acc = __ldg(b + c);
        const float* wc = ws + c*21;
        #pragma unroll
        for (int k = 0; k < DIN; k++) acc = fmaf(xv[k], wc[k], acc);
        acc = acc * scale + shift;
        acc = acc >= 0.f ? acc : 0.01f * acc;
        v[j] = acc;
        s += acc;
    }
    #pragma unroll
    for (int o = 16; o > 0; o >>= 1) s += __shfl_xor_sync(0xffffffffu, s, o);
    const float mu = s * (1.0f/256.0f);
    float q = 0.f;
    #pragma unroll
    for (int j = 0; j < 8; j++) { float d = v[j] - mu; q += d*d; }
    #pragma unroll
    for (int o = 16; o > 0; o >>= 1) q += __shfl_xor_sync(0xffffffffu, q, o);
    const float rstd = rsqrtf(q * (1.0f/256.0f) + EPSF);
    #pragma unroll
    for (int j = 0; j < 8; j++) {
        int c = lane + 32*j;
        g_xln[row*DMODEL + c] = (v[j] - mu) * rstd * __ldg(ln_g + c) + __ldg(ln_b + c);
    }
}

// ---------------- selective scan ----------------
__global__ __launch_bounds__(128)
void k_scan(const float* __restrict__ A_log, const float* __restrict__ Dp,
            const float* __restrict__ dtb,
            const float* __restrict__ convw, const float* __restrict__ convb) {
    int b = blockIdx.x;
    int d = blockIdx.y * 128 + threadIdx.x;
    float A0 = -expf(A_log[d*4+0]);
    float A1 = -expf(A_log[d*4+1]);
    float A2 = -expf(A_log[d*4+2]);
    float A3 = -expf(A_log[d*4+3]);
    float Dd = Dp[d];
    float bdt = dtb[d];
    float w0 = convw[2*d], w1 = convw[2*d+1], cb = convb[d];
    float h0 = 0.f, h1 = 0.f, h2 = 0.f, h3 = 0.f;
    float up = 0.f;
    const size_t base_row = (size_t)b * SEQ;
    float u_n   = g_xz[(base_row)*DX2 + d];
    float z_n   = g_xz[(base_row)*DX2 + DINNER + d];
    float dtp_n = g_dbl2[(base_row)*NCOMB + d];
    float4 bc0_n = *(const float4*)(g_dbl2 + (base_row)*NCOMB + 256);
    float4 bc1_n = *(const float4*)(g_dbl2 + (base_row)*NCOMB + 260);
    for (int t = 0; t < SEQ; t++) {
        float u = u_n, z = z_n, dtp0 = dtp_n;
        float4 bc0 = bc0_n, bc1 = bc1_n;
        if (t + 1 < SEQ) {
            size_t row1 = base_row + t + 1;
            u_n   = g_xz[row1*DX2 + d];
            z_n   = g_xz[row1*DX2 + DINNER + d];
            dtp_n = g_dbl2[row1*NCOMB + d];
            bc0_n = *(const float4*)(g_dbl2 + row1*NCOMB + 256);
            bc1_n = *(const float4*)(g_dbl2 + row1*NCOMB + 260);
        }
        float cv  = fmaf(up, w0, fmaf(u, w1, cb));
        float xc  = cv / (1.f + __expf(-cv));
        up = u;
        float dtp = dtp0 + bdt;
        float dt  = fmaxf(dtp, 0.f) + log1pf(__expf(-fabsf(dtp)));
        float dtxc = dt * xc;
        h0 = fmaf(h0, __expf(dt * A0), dtxc * bc0.x);
        h1 = fmaf(h1, __expf(dt * A1), dtxc * bc0.y);
        h2 = fmaf(h2, __expf(dt * A2), dtxc * bc0.z);
        h3 = fmaf(h3, __expf(dt * A3), dtxc * bc0.w);
        float y = h0*bc1.x + h1*bc1.y + h2*bc1.z + h3*bc1.w;
        y = fmaf(Dd, xc, y);
        float sz = z / (1.f + __expf(-z));
        g_y[(base_row + t) * DINNER + d] = y * sz;
    }
}

// ---------------- final: grid (176, 8); fused sigmoid via completion counter ----------------
__global__ __launch_bounds__(256)
void k_final(float* __restrict__ out) {
    __shared__ float sW[15][CHUNK2];
    __shared__ int isLast;
    const int cx = blockIdx.x;
    const int bg = blockIdx.y;
    const int k0 = cx * CHUNK2;
    const int tid = threadIdx.x;
    for (int idx = tid; idx < 15*(CHUNK2/4); idx += 256) {
        int i = idx / (CHUNK2/4), k4 = idx - i*(CHUNK2/4);
        *(float4*)&sW[i][k4*4] = *(const float4*)(g_Whead2 + (size_t)i*KHEAD + k0 + k4*4);
    }
    __syncthreads();
    const int w = tid >> 5, lane = tid & 31;
    #pragma unroll
    for (int bi = 0; bi < 2; bi++) {
        int b = bg * 16 + w * 2 + bi;
        const float4* yp = (const float4*)(g_y + (size_t)b * KHEAD + k0);
        float4 ya = yp[lane*2], yb = yp[lane*2 + 1];
        #pragma unroll 1
        for (int i = 0; i < 15; i++) {
            float4 wa = *(const float4*)&sW[i][lane*8];
            float4 wb = *(const float4*)&sW[i][lane*8 + 4];
            float s = ya.x*wa.x + ya.y*wa.y + ya.z*wa.z + ya.w*wa.w
                    + yb.x*wb.x + yb.y*wb.y + yb.z*wb.z + yb.w*wb.w;
            #pragma unroll
            for (int o = 16; o > 0; o >>= 1) s += __shfl_xor_sync(0xffffffffu, s, o);
            if (lane == 0) atomicAdd(&g_acc[i*128 + b], s);
        }
    }
    __threadfence();
    if (tid == 0) {
        int t = atomicAdd(&g_done, 1);
        isLast = (t == NCHUNK*8 - 1);
    }
    __syncthreads();
    if (isLast) {
        __threadfence();
        for (int p = tid; p < 15*128; p += 256) {
            int b = p / 15, i = p - b*15;
            out[p] = 1.f / (1.f + expf(-(g_acc[i*128 + b] + g_bhead[i])));
        }
    }
}

// ---------------- launch ----------------
extern "C" void kernel_launch(void* const* d_in, const int* in_sizes, int n_in,
                              void* d_out, int out_size) {
    const float* x         = (const float*)d_in[0];
    const float* lin1_w    = (const float*)d_in[1];
    const float* lin1_b    = (const float*)d_in[2];
    const float* bn1_g     = (const float*)d_in[3];
    const float* bn1_b     = (const float*)d_in[4];
    const float* ln_g      = (const float*)d_in[5];
    const float* ln_b      = (const float*)d_in[6];
    const float* in_proj_w = (const float*)d_in[7];
    const float* conv_w    = (const float*)d_in[8];
    const float* conv_b    = (const float*)d_in[9];
    const float* x_proj_w  = (const float*)d_in[10];
    const float* dt_proj_w = (const float*)d_in[11];
    const float* dt_proj_b = (const float*)d_in[12];
    const float* A_log     = (const float*)d_in[13];
    const float* Dp        = (const float*)d_in[14];
    const float* out_proj_w= (const float*)d_in[15];
    const float* bn5_g     = (const float*)d_in[16];
    const float* bn5_b     = (const float*)d_in[17];
    const float* l5a_w     = (const float*)d_in[18];
    const float* l5a_b     = (const float*)d_in[19];
    const float* l5b_w     = (const float*)d_in[20];
    const float* l5b_b     = (const float*)d_in[21];
    const float* l5c_w     = (const float*)d_in[22];
    const float* l5c_b     = (const float*)d_in[23];
    const float* fc3_w     = (const float*)d_in[24];
    const float* fc3_b     = (const float*)d_in[25];

    float *p_xln, *p_xz, *p_xc, *p_dbl2, *p_Wcomb;
    cudaGetSymbolAddress((void**)&p_xln,   g_xln);
    cudaGetSymbolAddress((void**)&p_xz,    g_xz);
    cudaGetSymbolAddress((void**)&p_xc,    g_xc);
    cudaGetSymbolAddress((void**)&p_dbl2,  g_dbl2);
    cudaGetSymbolAddress((void**)&p_Wcomb, g_Wcomb);

    cudaFuncSetAttribute(k_mma, cudaFuncAttributeMaxDynamicSharedMemorySize, SMEM_GEMM);

    const int GY = MROWS / 128;   // 176

    // 0: front (lin1+bn1+lrelu+LN)
    k_front<<<MROWS/8, 256>>>(x, lin1_w, lin1_b, bn1_g, bn1_b, ln_g, ln_b);
    // 1: pre1 (wcomb + t1/bc1/rs1)
    k_pre1<<<NCOMB + 64, 256>>>(dt_proj_w, x_proj_w, l5a_w, l5a_b, l5b_w, l5b_b);
    // 2: in_proj [M,256]@[512,256]^T
    k_mma<<<dim3(8, GY), 256, SMEM_GEMM>>>(p_xln, DMODEL, in_proj_w, p_xz, DX2, DMODEL);
    // 3: conv+silu elementwise   <-- profiled slot
    k_conv<<<(MROWS*64 + 255)/256, 256>>>(conv_w, conv_b);
    // 4: comb GEMM: xc @ Wcomb^T -> [M,264]
    k_mma<<<dim3(5, GY), 256, SMEM_GEMM>>>(p_xc, DINNER, p_Wcomb, p_dbl2, NCOMB, DINNER);
    // 5: T1W = T1 @ Wout
    k_t1w<<<64, 256>>>(out_proj_w);
    // 6: Wc2 rows + bias/zeroing
    k_wc2b<<<17, 256>>>(l5c_w, l5c_b, fc3_w, fc3_b, bn5_b);
    // 7: t3 -> Whead2
    k_t3<<<dim3(SEQ, 15), 256>>>(fc3_w, bn5_g);
    // 8: scan
    k_scan<<<dim3(BATCH, 2), 128>>>(A_log, Dp, dt_proj_b, conv_w, conv_b);
    // 9: final (+ fused sigmoid)
    k_final<<<dim3(NCHUNK, 8), 256>>>((float*)d_out);
}